// round 5
// baseline (speedup 1.0000x reference)
#include <cuda_runtime.h>
#include <stdint.h>
#include <math.h>

typedef unsigned int u32;
typedef unsigned long long u64;

#define NB    8
#define NAC   22500
#define NG    20
#define PRE   2000
#define POST  300
#define GRIDX 88                 // ceil(22500/256)
#define NPART (NB*GRIDX)         // 704

// ---------------- device scratch (no allocations allowed) ----------------
__device__ float g_anc[NAC*4];          // anchors xyxy
__device__ float g_actr[NAC*4];         // anchors cx,cy,w,h
__device__ unsigned char g_inside[NAC];
__device__ float g_prop[NB*NAC*4];      // clipped proposals
__device__ u64   g_K[NB*NAC];           // topk composite keys
__device__ u64   g_R[NB*NAC];           // rng composite keys
__device__ int   g_lab[NB*NAC];         // labels (pre- then post-sample)
__device__ unsigned char g_arg[NB*NAC]; // argmax gt per anchor
__device__ int   g_npos[NB], g_nneg[NB];
__device__ u64   g_posthr[NB], g_negthr[NB];
__device__ float g_sbox[NB*PRE*4];      // sorted top-2000 boxes
__device__ u32   g_nmsmask[NB*PRE*64];  // suppression bitmask rows
__device__ int   g_keep[NB*POST];
__device__ int   g_nkeep[NB];
__device__ double g_partC[NPART], g_partB[NPART];

// ---------------- helpers ----------------
__device__ __forceinline__ u32 asc_map(float f){
    u32 b = __float_as_uint(f);
    return (b & 0x80000000u) ? ~b : (b | 0x80000000u);
}

// exact (per-op IEEE rn, no FMA contraction) reference pairwise_iou element
__device__ __forceinline__ float iou_pair(float ax1,float ay1,float ax2,float ay2,
                                          float bx1,float by1,float bx2,float by2){
    float tlx = fmaxf(ax1,bx1), tly = fmaxf(ay1,by1);
    float brx = fminf(ax2,bx2), bry = fminf(ay2,by2);
    float w = fmaxf(__fsub_rn(brx, tlx), 0.0f);
    float h = fmaxf(__fsub_rn(bry, tly), 0.0f);
    float inter = __fmul_rn(w, h);
    float a1 = __fmul_rn(__fsub_rn(ax2,ax1), __fsub_rn(ay2,ay1));
    float a2 = __fmul_rn(__fsub_rn(bx2,bx1), __fsub_rn(by2,by1));
    float den = fmaxf(__fsub_rn(__fadd_rn(a1, a2), inter), 1e-8f);
    return __fdiv_rn(inter, den);
}

// jax threefry2x32, PARTITIONABLE scheme (jax_threefry_partitionable=True,
// default since jax 0.4.36): per-element uint64 counter i -> block inputs
// (hi32(i)=0, lo32(i)=i); 32-bit output = out0 ^ out1. Key = (0, 42).
#define TFR(r) { x0 += x1; x1 = (x1<<(r))|(x1>>(32-(r))); x1 ^= x0; }
__device__ __forceinline__ u32 tf_bits(u32 flat){
    const u32 k0 = 0u, k1 = 42u;
    const u32 k2 = 0x1BD11BDAu ^ k0 ^ k1;
    u32 x0 = 0u, x1 = flat;
    x0 += k0; x1 += k1;
    TFR(13) TFR(15) TFR(26) TFR(6)
    x0 += k1; x1 += k2 + 1u;
    TFR(17) TFR(29) TFR(16) TFR(24)
    x0 += k2; x1 += k0 + 2u;
    TFR(13) TFR(15) TFR(26) TFR(6)
    x0 += k0; x1 += k1 + 3u;
    TFR(17) TFR(29) TFR(16) TFR(24)
    x0 += k1; x1 += k2 + 4u;
    TFR(13) TFR(15) TFR(26) TFR(6)
    x0 += k2; x1 += k0 + 5u;
    return x0 ^ x1;
}
#undef TFR

// block-cooperative kth-smallest (1-indexed) u64 radix select over optionally
// label-filtered array. All keys distinct. Returns the kth key (all threads).
__device__ u64 kth_u64(const u64* keys, const int* lab, int want, int n,
                       unsigned k, u32* hist, u64* s_pref, unsigned* s_k){
    u64 pref = 0;
    unsigned kk = k;
    for (int pass = 0; pass < 8; pass++){
        int shift = 56 - 8*pass;
        for (int i = threadIdx.x; i < 256; i += blockDim.x) hist[i] = 0;
        __syncthreads();
        for (int e = threadIdx.x; e < n; e += blockDim.x){
            if (lab && lab[e] != want) continue;
            u64 key = keys[e];
            bool ok = (pass == 0) || ((key >> (unsigned)(shift + 8)) == pref);
            if (ok) atomicAdd(&hist[(unsigned)(key >> shift) & 255u], 1u);
        }
        __syncthreads();
        if (threadIdx.x == 0){
            unsigned cum = 0; int bin = 0;
            for (; bin < 256; bin++){
                unsigned cc = hist[bin];
                if (cum + cc >= kk) break;
                cum += cc;
            }
            *s_pref = (pref << 8) | (u64)(unsigned)bin;
            *s_k = kk - cum;
        }
        __syncthreads();
        pref = *s_pref; kk = *s_k;
        __syncthreads();
    }
    return pref;
}

// ---------------- K0: anchors ----------------
__global__ void k_init(){
    int n = blockIdx.x*blockDim.x + threadIdx.x;
    if (n >= NAC) return;
    int d = n / 2500, c = n % 2500;
    int si = d / 3, ri = d % 3;
    double s = (si==0) ? 8.0 : (si==1) ? 16.0 : 32.0;
    double r = (ri==0) ? 0.5 : (ri==1) ? 1.0 : 2.0;
    float d0 = (float)(16.0 * s * sqrt(r));
    float d1 = (float)(16.0 * s * sqrt(1.0 / r));
    float cx = (float)(8 + 16*(c/50));
    float cy = (float)(8 + 16*(c%50));
    float hx = __fmul_rn(0.5f, d0), hy = __fmul_rn(0.5f, d1);
    float x1 = __fsub_rn(cx, hx), y1 = __fsub_rn(cy, hy);
    float x2 = __fadd_rn(cx, hx), y2 = __fadd_rn(cy, hy);
    g_anc[n*4+0]=x1; g_anc[n*4+1]=y1; g_anc[n*4+2]=x2; g_anc[n*4+3]=y2;
    g_actr[n*4+0]=__fmul_rn(__fadd_rn(x1,x2),0.5f);
    g_actr[n*4+1]=__fmul_rn(__fadd_rn(y1,y2),0.5f);
    g_actr[n*4+2]=__fsub_rn(x2,x1);
    g_actr[n*4+3]=__fsub_rn(y2,y1);
    g_inside[n] = (x1 >= 0.0f) && (y1 >= 0.0f) && (x2 <= 800.0f) && (y2 <= 800.0f);
}

// ---------------- K1: decode proposals + score keys ----------------
__global__ void k_decode(const float* __restrict__ pred, const float* __restrict__ cls){
    int n = blockIdx.x*blockDim.x + threadIdx.x;
    int b = blockIdx.y;
    if (n >= NAC) return;
    int hw = n / 9, a = n % 9, h = hw / 50, w = hw % 50;
    size_t pbase = (((size_t)b*36 + (size_t)a*4)*50 + h)*50 + w;
    float dx = pred[pbase], dy = pred[pbase+2500], dw = pred[pbase+5000], dh = pred[pbase+7500];
    float ax = g_actr[n*4+0], ay = g_actr[n*4+1], aw = g_actr[n*4+2], ah = g_actr[n*4+3];
    float px = __fadd_rn(ax, __fmul_rn(dx, aw));
    float py = __fadd_rn(ay, __fmul_rn(dy, ah));
    float pw = __fmul_rn(aw, expf(dw));
    float ph = __fmul_rn(ah, expf(dh));
    float hx = __fmul_rn(0.5f, pw), hy = __fmul_rn(0.5f, ph);
    float x1 = fminf(fmaxf(__fsub_rn(px, hx), 0.0f), 799.0f);
    float y1 = fminf(fmaxf(__fsub_rn(py, hy), 0.0f), 799.0f);
    float x2 = fminf(fmaxf(__fadd_rn(px, hx), 0.0f), 799.0f);
    float y2 = fminf(fmaxf(__fadd_rn(py, hy), 0.0f), 799.0f);
    size_t o = ((size_t)b*NAC + n)*4;
    *(float4*)(g_prop + o) = make_float4(x1, y1, x2, y2);
    float sc = cls[(((size_t)b*18 + 9 + a)*50 + h)*50 + w];
    g_K[(size_t)b*NAC + n] = ((u64)(~asc_map(sc)) << 32) | (u32)n;
}

// ---------------- K2: per-anchor labels, argmax gt, rng keys ----------------
__global__ void k_labels(const float* __restrict__ gt){
    __shared__ float sgt[NG*4];
    int b = blockIdx.y;
    if (threadIdx.x < NG*4) sgt[threadIdx.x] = gt[(size_t)b*NG*4 + threadIdx.x];
    __syncthreads();
    int n = blockIdx.x*blockDim.x + threadIdx.x;
    if (n >= NAC) return;
    float bx1 = g_anc[n*4+0], by1 = g_anc[n*4+1], bx2 = g_anc[n*4+2], by2 = g_anc[n*4+3];
    float best = -1.0f; int bg = 0;
    #pragma unroll
    for (int g = 0; g < NG; g++){
        float v = iou_pair(sgt[g*4+0], sgt[g*4+1], sgt[g*4+2], sgt[g*4+3],
                           bx1, by1, bx2, by2);
        if (v > best){ best = v; bg = g; }
    }
    int lab = -1;
    if (best < 0.3f) lab = 0;
    if (best >= 0.7f) lab = 1;
    if (g_inside[n]) lab = -1;
    size_t idx = (size_t)b*NAC + n;
    g_lab[idx] = lab;
    g_arg[idx] = (unsigned char)bg;
    u32 flat = (u32)idx;
    u32 bits = tf_bits(flat);
    g_R[idx] = ((u64)(bits >> 9) << 32) | (u32)n;
}

// ---------------- K3: per-gt best anchor -> label 1 (unless inside) --------
__global__ void k_gtbest(const float* __restrict__ gt){
    __shared__ float sv[256];
    __shared__ int sn[256];
    int b = blockIdx.y, g = blockIdx.x;
    float gx1 = gt[((size_t)b*NG+g)*4+0], gy1 = gt[((size_t)b*NG+g)*4+1];
    float gx2 = gt[((size_t)b*NG+g)*4+2], gy2 = gt[((size_t)b*NG+g)*4+3];
    float bv = -1.0f; int bn = 0;
    for (int n = threadIdx.x; n < NAC; n += blockDim.x){
        float v = iou_pair(gx1,gy1,gx2,gy2,
                           g_anc[n*4+0],g_anc[n*4+1],g_anc[n*4+2],g_anc[n*4+3]);
        if (v > bv || (v == bv && n < bn)){ bv = v; bn = n; }
    }
    sv[threadIdx.x] = bv; sn[threadIdx.x] = bn;
    __syncthreads();
    for (int o = 128; o > 0; o >>= 1){
        if (threadIdx.x < o){
            float v2 = sv[threadIdx.x+o]; int n2 = sn[threadIdx.x+o];
            if (v2 > sv[threadIdx.x] || (v2 == sv[threadIdx.x] && n2 < sn[threadIdx.x])){
                sv[threadIdx.x] = v2; sn[threadIdx.x] = n2;
            }
        }
        __syncthreads();
    }
    if (threadIdx.x == 0){
        int best = sn[0];
        if (!g_inside[best]) g_lab[(size_t)b*NAC + best] = 1;
    }
}

// ---------------- K4: counts ----------------
__global__ void k_count(){
    __shared__ int sp[256], sq[256];
    int b = blockIdx.x;
    int cp = 0, cn = 0;
    for (int n = threadIdx.x; n < NAC; n += blockDim.x){
        int l = g_lab[(size_t)b*NAC + n];
        cp += (l == 1); cn += (l == 0);
    }
    sp[threadIdx.x] = cp; sq[threadIdx.x] = cn;
    __syncthreads();
    for (int o = 128; o > 0; o >>= 1){
        if (threadIdx.x < o){ sp[threadIdx.x]+=sp[threadIdx.x+o]; sq[threadIdx.x]+=sq[threadIdx.x+o]; }
        __syncthreads();
    }
    if (threadIdx.x == 0){
        int np = min(sp[0], 128);
        int nn = min(sq[0], 256 - np);
        g_npos[b] = np; g_nneg[b] = nn;
    }
}

// ---------------- K5: sampling thresholds (radix select) -------------------
__global__ void k_select(){
    __shared__ u32 hist[256];
    __shared__ u64 sp; __shared__ unsigned sk;
    int b = blockIdx.x >> 1, c = blockIdx.x & 1;
    int want = (c == 0) ? 1 : 0;
    unsigned k = (c == 0) ? (unsigned)g_npos[b] : (unsigned)g_nneg[b];
    u64 thr = 0;
    if (k > 0)
        thr = kth_u64(g_R + (size_t)b*NAC, g_lab + (size_t)b*NAC, want, NAC, k, hist, &sp, &sk);
    if (threadIdx.x == 0){
        if (c == 0) g_posthr[b] = thr; else g_negthr[b] = thr;
    }
}

// ---------------- K6: final labels ----------------
__global__ void k_final(){
    int n = blockIdx.x*blockDim.x + threadIdx.x;
    int b = blockIdx.y;
    if (n >= NAC) return;
    size_t idx = (size_t)b*NAC + n;
    int lab = g_lab[idx];
    int out = -1;
    if (lab == 1 && g_npos[b] > 0 && g_R[idx] <= g_posthr[b]) out = 1;
    else if (lab == 0 && g_nneg[b] > 0 && g_R[idx] <= g_negthr[b]) out = 0;
    g_lab[idx] = out;
}

// ---------------- K7: top-2000 select + sort + gather boxes ----------------
__global__ void k_topk(){
    __shared__ u32 hist[256];
    __shared__ u64 sp; __shared__ unsigned sk; __shared__ unsigned scnt;
    __shared__ u64 buf[2048];
    int b = blockIdx.x, tid = threadIdx.x;
    const u64* keys = g_K + (size_t)b*NAC;
    u64 thr = kth_u64(keys, nullptr, 0, NAC, (unsigned)PRE, hist, &sp, &sk);
    if (tid == 0) scnt = 0;
    __syncthreads();
    for (int e = tid; e < NAC; e += blockDim.x){
        u64 key = keys[e];
        if (key <= thr){ unsigned p = atomicAdd(&scnt, 1u); buf[p] = key; }
    }
    __syncthreads();
    for (int e = PRE + tid; e < 2048; e += blockDim.x) buf[e] = ~0ull;
    __syncthreads();
    for (unsigned k2 = 2; k2 <= 2048; k2 <<= 1){
        for (unsigned j = k2 >> 1; j > 0; j >>= 1){
            for (unsigned i = tid; i < 2048; i += blockDim.x){
                unsigned ixj = i ^ j;
                if (ixj > i){
                    bool up = ((i & k2) == 0);
                    u64 a = buf[i], c = buf[ixj];
                    if ((a > c) == up){ buf[i] = c; buf[ixj] = a; }
                }
            }
            __syncthreads();
        }
    }
    for (int t = tid; t < PRE; t += blockDim.x){
        int n = (int)(buf[t] & 0xFFFFFFFFull);
        float4 v = *(const float4*)(g_prop + ((size_t)b*NAC + n)*4);
        *(float4*)(g_sbox + ((size_t)b*PRE + t)*4) = v;
    }
}

// ---------------- K8: NMS suppression bitmask ----------------
__global__ void k_mask(){
    __shared__ float sx1[PRE], sy1[PRE], sx2[PRE], sy2[PRE];
    int b = blockIdx.y, tile = blockIdx.x;
    const float* sb = g_sbox + (size_t)b*PRE*4;
    for (int j = threadIdx.x; j < PRE; j += blockDim.x){
        float4 v = ((const float4*)sb)[j];
        sx1[j]=v.x; sy1[j]=v.y; sx2[j]=v.z; sy2[j]=v.w;
    }
    __syncthreads();
    int warp = threadIdx.x >> 5, lane = threadIdx.x & 31;
    for (int rr = 0; rr < 4; rr++){
        int i = tile*32 + warp*4 + rr;
        if (i >= PRE) continue;
        float ax1 = sx1[i], ay1 = sy1[i], ax2 = sx2[i], ay2 = sy2[i];
        u32* out = g_nmsmask + ((size_t)b*PRE + i)*64;
        for (int cj = 0; cj < 63; cj++){
            int j = cj*32 + lane;
            bool bit = false;
            if (j < PRE && j > i){
                float iou = iou_pair(ax1, ay1, ax2, ay2, sx1[j], sy1[j], sx2[j], sy2[j]);
                bit = iou > 0.7f;
            }
            u32 word = __ballot_sync(0xffffffffu, bit);
            if (lane == 0) out[cj] = word;
        }
        if (lane == 0) out[63] = 0u;
    }
}

// ---------------- K9: serial greedy NMS reduce (1 warp / image) ------------
__global__ void k_nmsred(){
    int b = blockIdx.x, lane = threadIdx.x;
    u64 remv = 0ull;
    int cnt = 0;
    const u32* mbase = g_nmsmask + (size_t)b*PRE*64;
    for (int i = 0; i < PRE; i++){
        u64 wv = __shfl_sync(0xffffffffu, remv, i >> 6);
        bool sup = (wv >> (i & 63)) & 1ull;
        if (!sup){
            const u32* row = mbase + (size_t)i*64;
            u64 m = ((u64)__ldg(row + 2*lane + 1) << 32) | (u64)__ldg(row + 2*lane);
            remv |= m;
            if (lane == 0) g_keep[b*POST + cnt] = i;
            cnt++;
            if (cnt >= POST) break;
        }
    }
    if (lane == 0) g_nkeep[b] = cnt;
}

// ---------------- K10: write top boxes ----------------
__global__ void k_out(float* __restrict__ out){
    int t = blockIdx.x*blockDim.x + threadIdx.x;
    if (t >= NB*POST) return;
    int b = t / POST, j = t % POST;
    float4 v = make_float4(0.f, 0.f, 0.f, 0.f);
    if (j < g_nkeep[b]){
        int i = g_keep[b*POST + j];
        const float4 p = *(const float4*)(g_sbox + ((size_t)b*PRE + i)*4);
        v = make_float4(floorf(p.x), floorf(p.y), floorf(p.z), floorf(p.w));
    }
    ((float4*)out)[t] = v;
}

// ---------------- K11: losses (block partials, double) ---------------------
__global__ void k_loss(const float* __restrict__ pred, const float* __restrict__ cls,
                       const float* __restrict__ gt){
    __shared__ double s1[256], s2[256];
    int b = blockIdx.y;
    int n = blockIdx.x*blockDim.x + threadIdx.x;
    double cacc = 0.0, bacc = 0.0;
    if (n < NAC){
        size_t idx = (size_t)b*NAC + n;
        int lab = g_lab[idx];
        int hw = n / 9, a = n % 9, h = hw / 50, w = hw % 50;
        if (lab != -1){
            float x0 = cls[(((size_t)b*18 + a*2    )*50 + h)*50 + w];
            float x1 = cls[(((size_t)b*18 + a*2 + 1)*50 + h)*50 + w];
            float m = fmaxf(x0, x1);
            float l = logf(__fadd_rn(expf(__fsub_rn(x0, m)), expf(__fsub_rn(x1, m))));
            float sel = (lab == 1) ? x1 : x0;
            cacc = (double)__fsub_rn(l, __fsub_rn(sel, m));
        }
        if (lab == 1){
            float pd[4];
            size_t pbase = (((size_t)b*36 + (size_t)a*4)*50 + h)*50 + w;
            pd[0]=pred[pbase]; pd[1]=pred[pbase+2500]; pd[2]=pred[pbase+5000]; pd[3]=pred[pbase+7500];
            float ax = g_actr[n*4+0], ay = g_actr[n*4+1], aw = g_actr[n*4+2], ah = g_actr[n*4+3];
            int gi = g_arg[idx];
            const float* g4 = gt + ((size_t)b*NG + gi)*4;
            float gx = __fmul_rn(__fadd_rn(g4[0], g4[2]), 0.5f);
            float gy = __fmul_rn(__fadd_rn(g4[1], g4[3]), 0.5f);
            float gw = __fsub_rn(g4[2], g4[0]);
            float gh = __fsub_rn(g4[3], g4[1]);
            float tt[4];
            tt[0] = __fdiv_rn(__fsub_rn(gx, ax), aw);
            tt[1] = __fdiv_rn(__fsub_rn(gy, ay), ah);
            tt[2] = logf(__fdiv_rn(gw, aw));
            tt[3] = logf(__fdiv_rn(gh, ah));
            const float C1 = (float)(1.0/9.0), C2 = (float)(0.5/9.0);
            double s = 0.0;
            #pragma unroll
            for (int k = 0; k < 4; k++){
                float d = __fsub_rn(pd[k], tt[k]);
                float ad = fabsf(d);
                float l1 = (ad < C1) ? __fmul_rn(__fmul_rn(4.5f, d), d) : __fsub_rn(ad, C2);
                s += (double)l1;
            }
            bacc = s;
        }
    }
    s1[threadIdx.x] = cacc; s2[threadIdx.x] = bacc;
    __syncthreads();
    for (int o = 128; o > 0; o >>= 1){
        if (threadIdx.x < o){ s1[threadIdx.x]+=s1[threadIdx.x+o]; s2[threadIdx.x]+=s2[threadIdx.x+o]; }
        __syncthreads();
    }
    if (threadIdx.x == 0){
        int pb = b*GRIDX + blockIdx.x;
        g_partC[pb] = s1[0];
        g_partB[pb] = s2[0];
    }
}

__global__ void k_lossfin(float* __restrict__ out){
    __shared__ double s1[256], s2[256];
    double a = 0.0, c = 0.0;
    for (int i = threadIdx.x; i < NPART; i += blockDim.x){
        a += g_partC[i]; c += g_partB[i];
    }
    s1[threadIdx.x] = a; s2[threadIdx.x] = c;
    __syncthreads();
    for (int o = 128; o > 0; o >>= 1){
        if (threadIdx.x < o){ s1[threadIdx.x]+=s1[threadIdx.x+o]; s2[threadIdx.x]+=s2[threadIdx.x+o]; }
        __syncthreads();
    }
    if (threadIdx.x == 0){
        int tot = 0;
        for (int b = 0; b < NB; b++) tot += g_npos[b] + g_nneg[b];
        if (tot < 1) tot = 1;
        int N0 = g_npos[0] + g_nneg[0];
        if (N0 < 1) N0 = 1;
        out[NB*POST*4 + 0] = (float)(s2[0] / (double)N0);   // bbox_loss
        out[NB*POST*4 + 1] = (float)(s1[0] / (double)tot);  // cls_loss
    }
}

// ---------------- launch ----------------
extern "C" void kernel_launch(void* const* d_in, const int* in_sizes, int n_in,
                              void* d_out, int out_size){
    const float* pred = (const float*)d_in[0];
    const float* cls  = (const float*)d_in[1];
    const float* gt   = (const float*)d_in[2];
    float* out = (float*)d_out;
    (void)in_sizes; (void)n_in; (void)out_size;

    k_init  <<<GRIDX, 256>>>();
    k_decode<<<dim3(GRIDX, NB), 256>>>(pred, cls);
    k_labels<<<dim3(GRIDX, NB), 256>>>(gt);
    k_gtbest<<<dim3(NG, NB), 256>>>(gt);
    k_count <<<NB, 256>>>();
    k_select<<<NB*2, 256>>>();
    k_final <<<dim3(GRIDX, NB), 256>>>();
    k_topk  <<<NB, 256>>>();
    k_mask  <<<dim3(63, NB), 256>>>();
    k_nmsred<<<NB, 32>>>();
    k_out   <<<(NB*POST + 255)/256, 256>>>(out);
    k_loss  <<<dim3(GRIDX, NB), 256>>>(pred, cls, gt);
    k_lossfin<<<1, 256>>>(out);
}

// round 6
// speedup vs baseline: 2.0599x; 2.0599x over previous
#include <cuda_runtime.h>
#include <stdint.h>
#include <math.h>

typedef unsigned int u32;
typedef unsigned long long u64;

#define NB    8
#define NAC   22500
#define NG    20
#define PRE   2000
#define POST  300
#define GRIDX 88                 // ceil(22500/256)
#define NPART (NB*GRIDX)         // 704

// ---------------- device scratch (no allocations allowed) ----------------
__device__ float g_anc[NAC*4];          // anchors xyxy
__device__ float g_actr[NAC*4];         // anchors cx,cy,w,h
__device__ unsigned char g_inside[NAC];
__device__ float g_prop[NB*NAC*4];      // clipped proposals
__device__ u64   g_K[NB*NAC];           // topk composite keys
__device__ u64   g_R[NB*NAC];           // rng composite keys
__device__ int   g_lab[NB*NAC];         // labels (pre- then post-sample)
__device__ unsigned char g_arg[NB*NAC]; // argmax gt per anchor
__device__ u64   g_gtmin[NB*NG];        // per-gt best anchor (packed min)
__device__ int   g_npos[NB], g_nneg[NB];
__device__ u64   g_posthr[NB], g_negthr[NB];
__device__ float g_sbox[NB*PRE*4];      // sorted top-2000 boxes
__device__ u32   g_nmsmask[NB*PRE*64];  // suppression bitmask rows
__device__ int   g_keep[NB*POST];
__device__ int   g_nkeep[NB];
__device__ double g_partC[NPART], g_partB[NPART];

// radix pass byte positions (skip bytes that are 0 in all keys)
__device__ const int BPS_K[6] = {7,6,5,4,1,0};  // score hi = 32b, idx < 2^15
__device__ const int BPS_R[5] = {6,5,4,1,0};    // rng hi  = 23b, idx < 2^15

// ---------------- helpers ----------------
__device__ __forceinline__ u32 asc_map(float f){
    u32 b = __float_as_uint(f);
    return (b & 0x80000000u) ? ~b : (b | 0x80000000u);
}

// exact (per-op IEEE rn, no FMA contraction) reference pairwise_iou element
__device__ __forceinline__ float iou_pair(float ax1,float ay1,float ax2,float ay2,
                                          float bx1,float by1,float bx2,float by2){
    float tlx = fmaxf(ax1,bx1), tly = fmaxf(ay1,by1);
    float brx = fminf(ax2,bx2), bry = fminf(ay2,by2);
    float w = fmaxf(__fsub_rn(brx, tlx), 0.0f);
    float h = fmaxf(__fsub_rn(bry, tly), 0.0f);
    float inter = __fmul_rn(w, h);
    float a1 = __fmul_rn(__fsub_rn(ax2,ax1), __fsub_rn(ay2,ay1));
    float a2 = __fmul_rn(__fsub_rn(bx2,bx1), __fsub_rn(by2,by1));
    float den = fmaxf(__fsub_rn(__fadd_rn(a1, a2), inter), 1e-8f);
    return __fdiv_rn(inter, den);
}

// jax threefry2x32, PARTITIONABLE scheme: counter i -> (0, i); out = x0 ^ x1.
#define TFR(r) { x0 += x1; x1 = (x1<<(r))|(x1>>(32-(r))); x1 ^= x0; }
__device__ __forceinline__ u32 tf_bits(u32 flat){
    const u32 k0 = 0u, k1 = 42u;
    const u32 k2 = 0x1BD11BDAu ^ k0 ^ k1;
    u32 x0 = 0u, x1 = flat;
    x0 += k0; x1 += k1;
    TFR(13) TFR(15) TFR(26) TFR(6)
    x0 += k1; x1 += k2 + 1u;
    TFR(17) TFR(29) TFR(16) TFR(24)
    x0 += k2; x1 += k0 + 2u;
    TFR(13) TFR(15) TFR(26) TFR(6)
    x0 += k0; x1 += k1 + 3u;
    TFR(17) TFR(29) TFR(16) TFR(24)
    x0 += k1; x1 += k2 + 4u;
    TFR(13) TFR(15) TFR(26) TFR(6)
    x0 += k2; x1 += k0 + 5u;
    return x0 ^ x1;
}
#undef TFR

// block-cooperative kth-smallest (1-indexed) over selected byte positions.
// Skipped bytes must be zero in all keys. mask/pval formulation tolerates gaps.
__device__ u64 kth_gen(const u64* __restrict__ keys, const int* __restrict__ lab,
                       int want, unsigned k, const int* bps, int np,
                       u32* hist, u32* s_bin, u32* s_rem){
    u64 pval = 0, mask = 0;
    unsigned kk = k;
    for (int p = 0; p < np; p++){
        int sh = 8*bps[p];
        for (int i = threadIdx.x; i < 256; i += blockDim.x) hist[i] = 0;
        __syncthreads();
        for (int e = threadIdx.x; e < NAC; e += blockDim.x){
            if (lab && lab[e] != want) continue;
            u64 key = keys[e];
            if ((key & mask) == pval)
                atomicAdd(&hist[(unsigned)(key >> sh) & 255u], 1u);
        }
        __syncthreads();
        if (threadIdx.x < 32){
            int lane = threadIdx.x;
            u32 c[8]; u32 s = 0;
            #pragma unroll
            for (int t = 0; t < 8; t++){ c[t] = hist[lane*8+t]; s += c[t]; }
            u32 cum = s;
            #pragma unroll
            for (int o = 1; o < 32; o <<= 1){
                u32 v = __shfl_up_sync(0xffffffffu, cum, o);
                if (lane >= o) cum += v;
            }
            u32 excl = cum - s;
            bool has = (excl < kk) && (kk <= cum);
            u32 bal = __ballot_sync(0xffffffffu, has);
            int src = __ffs(bal) - 1;
            if (lane == src){
                u32 rem = kk - excl;
                int t = 0;
                while (rem > c[t]){ rem -= c[t]; t++; }
                *s_bin = (u32)(lane*8 + t);
                *s_rem = rem;
            }
        }
        __syncthreads();
        pval |= ((u64)(*s_bin)) << sh;
        mask |= ((u64)255u) << sh;
        kk = *s_rem;
        __syncthreads();
    }
    return pval;
}

// ---------------- K0: anchors + resets ----------------
__global__ void k_init(){
    int n = blockIdx.x*blockDim.x + threadIdx.x;
    if (n < NB*NG) g_gtmin[n] = ~0ull;
    if (n >= NAC) return;
    int d = n / 2500, c = n % 2500;
    int si = d / 3, ri = d % 3;
    double s = (si==0) ? 8.0 : (si==1) ? 16.0 : 32.0;
    double r = (ri==0) ? 0.5 : (ri==1) ? 1.0 : 2.0;
    float d0 = (float)(16.0 * s * sqrt(r));
    float d1 = (float)(16.0 * s * sqrt(1.0 / r));
    float cx = (float)(8 + 16*(c/50));
    float cy = (float)(8 + 16*(c%50));
    float hx = __fmul_rn(0.5f, d0), hy = __fmul_rn(0.5f, d1);
    float x1 = __fsub_rn(cx, hx), y1 = __fsub_rn(cy, hy);
    float x2 = __fadd_rn(cx, hx), y2 = __fadd_rn(cy, hy);
    g_anc[n*4+0]=x1; g_anc[n*4+1]=y1; g_anc[n*4+2]=x2; g_anc[n*4+3]=y2;
    g_actr[n*4+0]=__fmul_rn(__fadd_rn(x1,x2),0.5f);
    g_actr[n*4+1]=__fmul_rn(__fadd_rn(y1,y2),0.5f);
    g_actr[n*4+2]=__fsub_rn(x2,x1);
    g_actr[n*4+3]=__fsub_rn(y2,y1);
    g_inside[n] = (x1 >= 0.0f) && (y1 >= 0.0f) && (x2 <= 800.0f) && (y2 <= 800.0f);
}

// ---------------- K1: decode proposals + score keys ----------------
__global__ void k_decode(const float* __restrict__ pred, const float* __restrict__ cls){
    int n = blockIdx.x*blockDim.x + threadIdx.x;
    int b = blockIdx.y;
    if (n >= NAC) return;
    int hw = n / 9, a = n % 9, h = hw / 50, w = hw % 50;
    size_t pbase = (((size_t)b*36 + (size_t)a*4)*50 + h)*50 + w;
    float dx = pred[pbase], dy = pred[pbase+2500], dw = pred[pbase+5000], dh = pred[pbase+7500];
    float ax = g_actr[n*4+0], ay = g_actr[n*4+1], aw = g_actr[n*4+2], ah = g_actr[n*4+3];
    float px = __fadd_rn(ax, __fmul_rn(dx, aw));
    float py = __fadd_rn(ay, __fmul_rn(dy, ah));
    float pw = __fmul_rn(aw, expf(dw));
    float ph = __fmul_rn(ah, expf(dh));
    float hx = __fmul_rn(0.5f, pw), hy = __fmul_rn(0.5f, ph);
    float x1 = fminf(fmaxf(__fsub_rn(px, hx), 0.0f), 799.0f);
    float y1 = fminf(fmaxf(__fsub_rn(py, hy), 0.0f), 799.0f);
    float x2 = fminf(fmaxf(__fadd_rn(px, hx), 0.0f), 799.0f);
    float y2 = fminf(fmaxf(__fadd_rn(py, hy), 0.0f), 799.0f);
    size_t o = ((size_t)b*NAC + n)*4;
    *(float4*)(g_prop + o) = make_float4(x1, y1, x2, y2);
    float sc = cls[(((size_t)b*18 + 9 + a)*50 + h)*50 + w];
    g_K[(size_t)b*NAC + n] = ((u64)(~asc_map(sc)) << 32) | (u32)n;
}

// ---------------- K2: labels + argmax + rng + fused per-gt best -----------
__global__ void k_labels(const float* __restrict__ gt){
    __shared__ float sgt[NG*4];
    __shared__ u64 sbest[NG];
    int b = blockIdx.y;
    if (threadIdx.x < NG*4) sgt[threadIdx.x] = gt[(size_t)b*NG*4 + threadIdx.x];
    if (threadIdx.x < NG) sbest[threadIdx.x] = ~0ull;
    __syncthreads();
    int n = blockIdx.x*blockDim.x + threadIdx.x;
    bool act = (n < NAC);
    int lane = threadIdx.x & 31;

    float iouv[NG];
    float best = -1.0f; int bg = 0;
    if (act){
        float bx1 = g_anc[n*4+0], by1 = g_anc[n*4+1], bx2 = g_anc[n*4+2], by2 = g_anc[n*4+3];
        #pragma unroll
        for (int g = 0; g < NG; g++){
            float v = iou_pair(sgt[g*4+0], sgt[g*4+1], sgt[g*4+2], sgt[g*4+3],
                               bx1, by1, bx2, by2);
            iouv[g] = v;
            if (v > best){ best = v; bg = g; }
        }
    }
    // per-gt best anchor: warp min-reduce packed (~asc(iou), n), then smem atomic
    #pragma unroll
    for (int g = 0; g < NG; g++){
        u64 pk = act ? ((((u64)(~asc_map(iouv[g]))) << 32) | (u32)n) : ~0ull;
        #pragma unroll
        for (int o = 16; o > 0; o >>= 1){
            u64 other = __shfl_down_sync(0xffffffffu, pk, o);
            pk = (other < pk) ? other : pk;
        }
        if (lane == 0) atomicMin((unsigned long long*)&sbest[g], (unsigned long long)pk);
    }
    __syncthreads();
    if (threadIdx.x < NG)
        atomicMin((unsigned long long*)&g_gtmin[b*NG + threadIdx.x],
                  (unsigned long long)sbest[threadIdx.x]);

    if (!act) return;
    int lab = -1;
    if (best < 0.3f) lab = 0;
    if (best >= 0.7f) lab = 1;
    if (g_inside[n]) lab = -1;
    size_t idx = (size_t)b*NAC + n;
    g_lab[idx] = lab;
    g_arg[idx] = (unsigned char)bg;
    u32 bits = tf_bits((u32)idx);
    g_R[idx] = ((u64)(bits >> 9) << 32) | (u32)n;
}

// ---------------- K3: apply per-gt best anchor -> label 1 ------------------
__global__ void k_gtapply(){
    int t = blockIdx.x*blockDim.x + threadIdx.x;
    if (t >= NB*NG) return;
    int b = t / NG;
    u64 v = g_gtmin[t];
    int n = (int)(v & 0xFFFFFFFFull);
    if (!g_inside[n]) g_lab[(size_t)b*NAC + n] = 1;
}

// ---------------- K4: fused count + sampling threshold select --------------
__global__ void __launch_bounds__(1024) k_select(){
    __shared__ u32 hist[256];
    __shared__ u32 s_bin, s_rem;
    __shared__ int scp, scn;
    int b = blockIdx.x >> 1, c = blockIdx.x & 1;
    const int* lab = g_lab + (size_t)b*NAC;
    if (threadIdx.x == 0){ scp = 0; scn = 0; }
    __syncthreads();
    int cp = 0, cn = 0;
    for (int e = threadIdx.x; e < NAC; e += blockDim.x){
        int l = lab[e];
        cp += (l == 1); cn += (l == 0);
    }
    #pragma unroll
    for (int o = 16; o > 0; o >>= 1){
        cp += __shfl_down_sync(0xffffffffu, cp, o);
        cn += __shfl_down_sync(0xffffffffu, cn, o);
    }
    if ((threadIdx.x & 31) == 0){ atomicAdd(&scp, cp); atomicAdd(&scn, cn); }
    __syncthreads();
    int np = min(scp, 128);
    int nn = min(scn, 256 - np);
    int want = (c == 0) ? 1 : 0;
    unsigned k = (c == 0) ? (unsigned)np : (unsigned)nn;
    u64 thr = 0;
    if (k > 0)
        thr = kth_gen(g_R + (size_t)b*NAC, lab, want, k, BPS_R, 5, hist, &s_bin, &s_rem);
    if (threadIdx.x == 0){
        if (c == 0){ g_posthr[b] = thr; g_npos[b] = np; }
        else       { g_negthr[b] = thr; g_nneg[b] = nn; }
    }
}

// ---------------- K5: final labels ----------------
__global__ void k_final(){
    int n = blockIdx.x*blockDim.x + threadIdx.x;
    int b = blockIdx.y;
    if (n >= NAC) return;
    size_t idx = (size_t)b*NAC + n;
    int lab = g_lab[idx];
    int out = -1;
    if (lab == 1 && g_npos[b] > 0 && g_R[idx] <= g_posthr[b]) out = 1;
    else if (lab == 0 && g_nneg[b] > 0 && g_R[idx] <= g_negthr[b]) out = 0;
    g_lab[idx] = out;
}

// ---------------- K6: top-2000 select + sort + gather boxes ----------------
__global__ void __launch_bounds__(1024) k_topk(){
    __shared__ u32 hist[256];
    __shared__ u32 s_bin, s_rem;
    __shared__ unsigned scnt;
    __shared__ u64 buf[2048];
    int b = blockIdx.x, tid = threadIdx.x;
    const u64* keys = g_K + (size_t)b*NAC;
    u64 thr = kth_gen(keys, nullptr, 0, (unsigned)PRE, BPS_K, 6, hist, &s_bin, &s_rem);
    if (tid == 0) scnt = 0;
    __syncthreads();
    for (int e = tid; e < NAC; e += blockDim.x){
        u64 key = keys[e];
        if (key <= thr){ unsigned p = atomicAdd(&scnt, 1u); buf[p] = key; }
    }
    __syncthreads();
    for (int e = PRE + tid; e < 2048; e += blockDim.x) buf[e] = ~0ull;
    __syncthreads();
    for (unsigned k2 = 2; k2 <= 2048; k2 <<= 1){
        for (unsigned j = k2 >> 1; j > 0; j >>= 1){
            for (unsigned i = tid; i < 2048; i += blockDim.x){
                unsigned ixj = i ^ j;
                if (ixj > i){
                    bool up = ((i & k2) == 0);
                    u64 a = buf[i], cc = buf[ixj];
                    if ((a > cc) == up){ buf[i] = cc; buf[ixj] = a; }
                }
            }
            __syncthreads();
        }
    }
    for (int t = tid; t < PRE; t += blockDim.x){
        int n = (int)(buf[t] & 0xFFFFFFFFull);
        float4 v = *(const float4*)(g_prop + ((size_t)b*NAC + n)*4);
        *(float4*)(g_sbox + ((size_t)b*PRE + t)*4) = v;
    }
}

// ---------------- K7: NMS suppression bitmask (upper triangle only) --------
__global__ void k_mask(){
    __shared__ float sx1[PRE], sy1[PRE], sx2[PRE], sy2[PRE];
    int b = blockIdx.y, tile = blockIdx.x;
    const float* sb = g_sbox + (size_t)b*PRE*4;
    for (int j = threadIdx.x; j < PRE; j += blockDim.x){
        float4 v = ((const float4*)sb)[j];
        sx1[j]=v.x; sy1[j]=v.y; sx2[j]=v.z; sy2[j]=v.w;
    }
    __syncthreads();
    int warp = threadIdx.x >> 5, lane = threadIdx.x & 31;
    for (int rr = 0; rr < 4; rr++){
        int i = tile*32 + warp*4 + rr;
        if (i >= PRE) continue;
        float ax1 = sx1[i], ay1 = sy1[i], ax2 = sx2[i], ay2 = sy2[i];
        u32* out = g_nmsmask + ((size_t)b*PRE + i)*64;
        int cj0 = i >> 5;
        for (int cj = lane; cj < cj0; cj += 32) out[cj] = 0u;
        for (int cj = cj0; cj < 63; cj++){
            int j = cj*32 + lane;
            bool bit = false;
            if (j < PRE && j > i){
                float iou = iou_pair(ax1, ay1, ax2, ay2, sx1[j], sy1[j], sx2[j], sy2[j]);
                bit = iou > 0.7f;
            }
            u32 word = __ballot_sync(0xffffffffu, bit);
            if (lane == 0) out[cj] = word;
        }
        if (lane == 0) out[63] = 0u;
    }
}

// ---------------- K8: greedy NMS reduce, skip-scan over kept boxes ---------
__global__ void k_nmsred(){
    int b = blockIdx.x, lane = threadIdx.x;
    // lane owns suppression bits [64*lane, 64*lane+64)
    u64 rem = (lane == 31) ? ~((1ull << (PRE - 1984)) - 1ull) : 0ull;
    int cnt = 0, cur = 0;
    const u32* mbase = g_nmsmask + (size_t)b*PRE*64;
    while (cnt < POST){
        u64 myw = rem;
        int base = lane*64;
        if (cur >= base + 64) myw = ~0ull;
        else if (cur > base){
            int sh = cur - base;
            myw |= (sh ? ((1ull << sh) - 1ull) : 0ull);
        }
        u32 bal = __ballot_sync(0xffffffffu, myw != ~0ull);
        if (!bal) break;
        int src = __ffs(bal) - 1;
        u64 w = __shfl_sync(0xffffffffu, myw, src);
        int bit = __ffsll((long long)~w) - 1;
        int i = src*64 + bit;
        if (lane == 0) g_keep[b*POST + cnt] = i;
        cnt++;
        if (cnt >= POST) break;
        const u32* row = mbase + (size_t)i*64;
        u64 m = ((u64)__ldg(row + 2*lane + 1) << 32) | (u64)__ldg(row + 2*lane);
        rem |= m;
        cur = i + 1;
    }
    if (lane == 0) g_nkeep[b] = cnt;
}

// ---------------- K9: write top boxes ----------------
__global__ void k_out(float* __restrict__ out){
    int t = blockIdx.x*blockDim.x + threadIdx.x;
    if (t >= NB*POST) return;
    int b = t / POST, j = t % POST;
    float4 v = make_float4(0.f, 0.f, 0.f, 0.f);
    if (j < g_nkeep[b]){
        int i = g_keep[b*POST + j];
        const float4 p = *(const float4*)(g_sbox + ((size_t)b*PRE + i)*4);
        v = make_float4(floorf(p.x), floorf(p.y), floorf(p.z), floorf(p.w));
    }
    ((float4*)out)[t] = v;
}

// ---------------- K10: losses (block partials, double) ---------------------
__global__ void k_loss(const float* __restrict__ pred, const float* __restrict__ cls,
                       const float* __restrict__ gt){
    __shared__ double s1[256], s2[256];
    int b = blockIdx.y;
    int n = blockIdx.x*blockDim.x + threadIdx.x;
    double cacc = 0.0, bacc = 0.0;
    if (n < NAC){
        size_t idx = (size_t)b*NAC + n;
        int lab = g_lab[idx];
        int hw = n / 9, a = n % 9, h = hw / 50, w = hw % 50;
        if (lab != -1){
            float x0 = cls[(((size_t)b*18 + a*2    )*50 + h)*50 + w];
            float x1 = cls[(((size_t)b*18 + a*2 + 1)*50 + h)*50 + w];
            float m = fmaxf(x0, x1);
            float l = logf(__fadd_rn(expf(__fsub_rn(x0, m)), expf(__fsub_rn(x1, m))));
            float sel = (lab == 1) ? x1 : x0;
            cacc = (double)__fsub_rn(l, __fsub_rn(sel, m));
        }
        if (lab == 1){
            float pd[4];
            size_t pbase = (((size_t)b*36 + (size_t)a*4)*50 + h)*50 + w;
            pd[0]=pred[pbase]; pd[1]=pred[pbase+2500]; pd[2]=pred[pbase+5000]; pd[3]=pred[pbase+7500];
            float ax = g_actr[n*4+0], ay = g_actr[n*4+1], aw = g_actr[n*4+2], ah = g_actr[n*4+3];
            int gi = g_arg[idx];
            const float* g4 = gt + ((size_t)b*NG + gi)*4;
            float gx = __fmul_rn(__fadd_rn(g4[0], g4[2]), 0.5f);
            float gy = __fmul_rn(__fadd_rn(g4[1], g4[3]), 0.5f);
            float gw = __fsub_rn(g4[2], g4[0]);
            float gh = __fsub_rn(g4[3], g4[1]);
            float tt[4];
            tt[0] = __fdiv_rn(__fsub_rn(gx, ax), aw);
            tt[1] = __fdiv_rn(__fsub_rn(gy, ay), ah);
            tt[2] = logf(__fdiv_rn(gw, aw));
            tt[3] = logf(__fdiv_rn(gh, ah));
            const float C1 = (float)(1.0/9.0), C2 = (float)(0.5/9.0);
            double s = 0.0;
            #pragma unroll
            for (int k = 0; k < 4; k++){
                float d = __fsub_rn(pd[k], tt[k]);
                float ad = fabsf(d);
                float l1 = (ad < C1) ? __fmul_rn(__fmul_rn(4.5f, d), d) : __fsub_rn(ad, C2);
                s += (double)l1;
            }
            bacc = s;
        }
    }
    s1[threadIdx.x] = cacc; s2[threadIdx.x] = bacc;
    __syncthreads();
    for (int o = 128; o > 0; o >>= 1){
        if (threadIdx.x < o){ s1[threadIdx.x]+=s1[threadIdx.x+o]; s2[threadIdx.x]+=s2[threadIdx.x+o]; }
        __syncthreads();
    }
    if (threadIdx.x == 0){
        int pb = b*GRIDX + blockIdx.x;
        g_partC[pb] = s1[0];
        g_partB[pb] = s2[0];
    }
}

__global__ void k_lossfin(float* __restrict__ out){
    __shared__ double s1[256], s2[256];
    double a = 0.0, c = 0.0;
    for (int i = threadIdx.x; i < NPART; i += blockDim.x){
        a += g_partC[i]; c += g_partB[i];
    }
    s1[threadIdx.x] = a; s2[threadIdx.x] = c;
    __syncthreads();
    for (int o = 128; o > 0; o >>= 1){
        if (threadIdx.x < o){ s1[threadIdx.x]+=s1[threadIdx.x+o]; s2[threadIdx.x]+=s2[threadIdx.x+o]; }
        __syncthreads();
    }
    if (threadIdx.x == 0){
        int tot = 0;
        for (int b = 0; b < NB; b++) tot += g_npos[b] + g_nneg[b];
        if (tot < 1) tot = 1;
        int N0 = g_npos[0] + g_nneg[0];
        if (N0 < 1) N0 = 1;
        out[NB*POST*4 + 0] = (float)(s2[0] / (double)N0);   // bbox_loss
        out[NB*POST*4 + 1] = (float)(s1[0] / (double)tot);  // cls_loss
    }
}

// ---------------- launch ----------------
extern "C" void kernel_launch(void* const* d_in, const int* in_sizes, int n_in,
                              void* d_out, int out_size){
    const float* pred = (const float*)d_in[0];
    const float* cls  = (const float*)d_in[1];
    const float* gt   = (const float*)d_in[2];
    float* out = (float*)d_out;
    (void)in_sizes; (void)n_in; (void)out_size;

    k_init   <<<GRIDX, 256>>>();
    k_decode <<<dim3(GRIDX, NB), 256>>>(pred, cls);
    k_labels <<<dim3(GRIDX, NB), 256>>>(gt);
    k_gtapply<<<1, NB*NG>>>();
    k_select <<<NB*2, 1024>>>();
    k_final  <<<dim3(GRIDX, NB), 256>>>();
    k_topk   <<<NB, 1024>>>();
    k_mask   <<<dim3(63, NB), 256>>>();
    k_nmsred <<<NB, 32>>>();
    k_out    <<<(NB*POST + 255)/256, 256>>>(out);
    k_loss   <<<dim3(GRIDX, NB), 256>>>(pred, cls, gt);
    k_lossfin<<<1, 256>>>(out);
}

// round 7
// speedup vs baseline: 2.1173x; 1.0279x over previous
#include <cuda_runtime.h>
#include <stdint.h>
#include <math.h>

typedef unsigned int u32;
typedef unsigned long long u64;

#define NB    8
#define NAC   22500
#define NG    20
#define PRE   2000
#define POST  300
#define GRIDX 88                 // ceil(22500/256)
#define NPART (NB*GRIDX)         // 704

// ---------------- device scratch (no allocations allowed) ----------------
__device__ float g_anc[NAC*4];          // anchors xyxy
__device__ float g_actr[NAC*4];         // anchors cx,cy,w,h
__device__ unsigned char g_inside[NAC];
__device__ float g_prop[NB*NAC*4];      // clipped proposals
__device__ u64   g_K[NB*NAC];           // topk composite keys
__device__ u64   g_R[NB*NAC];           // rng composite keys
__device__ int   g_lab[NB*NAC];         // labels (pre-sample + gt-forced)
__device__ unsigned char g_arg[NB*NAC]; // argmax gt per anchor
__device__ u64   g_gtmin[NB*NG];        // per-gt best anchor (packed min)
__device__ int   g_npos[NB], g_nneg[NB];
__device__ u64   g_posthr[NB], g_negthr[NB];
__device__ float g_sbox[NB*PRE*4];      // sorted top-2000 boxes
__device__ u32   g_nmsmask[NB*PRE*64];  // suppression bitmask rows
__device__ double g_partC[NPART], g_partB[NPART];

// radix pass byte positions (skip bytes that are 0 in all keys)
__device__ const int BPS_K[6] = {7,6,5,4,1,0};  // score hi = 32b, idx < 2^15
__device__ const int BPS_R[5] = {6,5,4,1,0};    // rng hi  = 23b, idx < 2^15

// ---------------- helpers ----------------
__device__ __forceinline__ u32 asc_map(float f){
    u32 b = __float_as_uint(f);
    return (b & 0x80000000u) ? ~b : (b | 0x80000000u);
}

// exact (per-op IEEE rn, no FMA contraction) reference pairwise_iou element
__device__ __forceinline__ float iou_pair(float ax1,float ay1,float ax2,float ay2,
                                          float bx1,float by1,float bx2,float by2){
    float tlx = fmaxf(ax1,bx1), tly = fmaxf(ay1,by1);
    float brx = fminf(ax2,bx2), bry = fminf(ay2,by2);
    float w = fmaxf(__fsub_rn(brx, tlx), 0.0f);
    float h = fmaxf(__fsub_rn(bry, tly), 0.0f);
    float inter = __fmul_rn(w, h);
    float a1 = __fmul_rn(__fsub_rn(ax2,ax1), __fsub_rn(ay2,ay1));
    float a2 = __fmul_rn(__fsub_rn(bx2,bx1), __fsub_rn(by2,by1));
    float den = fmaxf(__fsub_rn(__fadd_rn(a1, a2), inter), 1e-8f);
    return __fdiv_rn(inter, den);
}

// jax threefry2x32, PARTITIONABLE scheme: counter i -> (0, i); out = x0 ^ x1.
#define TFR(r) { x0 += x1; x1 = (x1<<(r))|(x1>>(32-(r))); x1 ^= x0; }
__device__ __forceinline__ u32 tf_bits(u32 flat){
    const u32 k0 = 0u, k1 = 42u;
    const u32 k2 = 0x1BD11BDAu ^ k0 ^ k1;
    u32 x0 = 0u, x1 = flat;
    x0 += k0; x1 += k1;
    TFR(13) TFR(15) TFR(26) TFR(6)
    x0 += k1; x1 += k2 + 1u;
    TFR(17) TFR(29) TFR(16) TFR(24)
    x0 += k2; x1 += k0 + 2u;
    TFR(13) TFR(15) TFR(26) TFR(6)
    x0 += k0; x1 += k1 + 3u;
    TFR(17) TFR(29) TFR(16) TFR(24)
    x0 += k1; x1 += k2 + 4u;
    TFR(13) TFR(15) TFR(26) TFR(6)
    x0 += k2; x1 += k0 + 5u;
    return x0 ^ x1;
}
#undef TFR

// block-cooperative kth-smallest (1-indexed) over selected byte positions.
__device__ u64 kth_gen(const u64* __restrict__ keys, const int* __restrict__ lab,
                       int want, unsigned k, const int* bps, int np,
                       u32* hist, u32* s_bin, u32* s_rem){
    u64 pval = 0, mask = 0;
    unsigned kk = k;
    for (int p = 0; p < np; p++){
        int sh = 8*bps[p];
        for (int i = threadIdx.x; i < 256; i += blockDim.x) hist[i] = 0;
        __syncthreads();
        for (int e = threadIdx.x; e < NAC; e += blockDim.x){
            if (lab && lab[e] != want) continue;
            u64 key = keys[e];
            if ((key & mask) == pval)
                atomicAdd(&hist[(unsigned)(key >> sh) & 255u], 1u);
        }
        __syncthreads();
        if (threadIdx.x < 32){
            int lane = threadIdx.x;
            u32 c[8]; u32 s = 0;
            #pragma unroll
            for (int t = 0; t < 8; t++){ c[t] = hist[lane*8+t]; s += c[t]; }
            u32 cum = s;
            #pragma unroll
            for (int o = 1; o < 32; o <<= 1){
                u32 v = __shfl_up_sync(0xffffffffu, cum, o);
                if (lane >= o) cum += v;
            }
            u32 excl = cum - s;
            bool has = (excl < kk) && (kk <= cum);
            u32 bal = __ballot_sync(0xffffffffu, has);
            int src = __ffs(bal) - 1;
            if (lane == src){
                u32 rem = kk - excl;
                int t = 0;
                while (rem > c[t]){ rem -= c[t]; t++; }
                *s_bin = (u32)(lane*8 + t);
                *s_rem = rem;
            }
        }
        __syncthreads();
        pval |= ((u64)(*s_bin)) << sh;
        mask |= ((u64)255u) << sh;
        kk = *s_rem;
        __syncthreads();
    }
    return pval;
}

// ---------------- K0: anchors + resets ----------------
__global__ void k_init(){
    int n = blockIdx.x*blockDim.x + threadIdx.x;
    if (n < NB*NG) g_gtmin[n] = ~0ull;
    if (n >= NAC) return;
    int d = n / 2500, c = n % 2500;
    int si = d / 3, ri = d % 3;
    double s = (si==0) ? 8.0 : (si==1) ? 16.0 : 32.0;
    double r = (ri==0) ? 0.5 : (ri==1) ? 1.0 : 2.0;
    float d0 = (float)(16.0 * s * sqrt(r));
    float d1 = (float)(16.0 * s * sqrt(1.0 / r));
    float cx = (float)(8 + 16*(c/50));
    float cy = (float)(8 + 16*(c%50));
    float hx = __fmul_rn(0.5f, d0), hy = __fmul_rn(0.5f, d1);
    float x1 = __fsub_rn(cx, hx), y1 = __fsub_rn(cy, hy);
    float x2 = __fadd_rn(cx, hx), y2 = __fadd_rn(cy, hy);
    g_anc[n*4+0]=x1; g_anc[n*4+1]=y1; g_anc[n*4+2]=x2; g_anc[n*4+3]=y2;
    g_actr[n*4+0]=__fmul_rn(__fadd_rn(x1,x2),0.5f);
    g_actr[n*4+1]=__fmul_rn(__fadd_rn(y1,y2),0.5f);
    g_actr[n*4+2]=__fsub_rn(x2,x1);
    g_actr[n*4+3]=__fsub_rn(y2,y1);
    g_inside[n] = (x1 >= 0.0f) && (y1 >= 0.0f) && (x2 <= 800.0f) && (y2 <= 800.0f);
}

// ---------------- A1: decode proposals + score keys ----------------
__global__ void k_decode(const float* __restrict__ pred, const float* __restrict__ cls){
    int n = blockIdx.x*blockDim.x + threadIdx.x;
    int b = blockIdx.y;
    if (n >= NAC) return;
    int hw = n / 9, a = n % 9, h = hw / 50, w = hw % 50;
    size_t pbase = (((size_t)b*36 + (size_t)a*4)*50 + h)*50 + w;
    float dx = pred[pbase], dy = pred[pbase+2500], dw = pred[pbase+5000], dh = pred[pbase+7500];
    float ax = g_actr[n*4+0], ay = g_actr[n*4+1], aw = g_actr[n*4+2], ah = g_actr[n*4+3];
    float px = __fadd_rn(ax, __fmul_rn(dx, aw));
    float py = __fadd_rn(ay, __fmul_rn(dy, ah));
    float pw = __fmul_rn(aw, expf(dw));
    float ph = __fmul_rn(ah, expf(dh));
    float hx = __fmul_rn(0.5f, pw), hy = __fmul_rn(0.5f, ph);
    float x1 = fminf(fmaxf(__fsub_rn(px, hx), 0.0f), 799.0f);
    float y1 = fminf(fmaxf(__fsub_rn(py, hy), 0.0f), 799.0f);
    float x2 = fminf(fmaxf(__fadd_rn(px, hx), 0.0f), 799.0f);
    float y2 = fminf(fmaxf(__fadd_rn(py, hy), 0.0f), 799.0f);
    size_t o = ((size_t)b*NAC + n)*4;
    *(float4*)(g_prop + o) = make_float4(x1, y1, x2, y2);
    float sc = cls[(((size_t)b*18 + 9 + a)*50 + h)*50 + w];
    g_K[(size_t)b*NAC + n] = ((u64)(~asc_map(sc)) << 32) | (u32)n;
}

// ---------------- B1: labels + argmax + rng + per-gt best ------------------
__global__ void k_labels(const float* __restrict__ gt){
    __shared__ float sgt[NG*4];
    __shared__ u64 sbest[NG];
    int b = blockIdx.y;
    if (threadIdx.x < NG*4) sgt[threadIdx.x] = gt[(size_t)b*NG*4 + threadIdx.x];
    if (threadIdx.x < NG) sbest[threadIdx.x] = ~0ull;
    __syncthreads();
    int n = blockIdx.x*blockDim.x + threadIdx.x;
    bool act = (n < NAC);
    int lane = threadIdx.x & 31;

    float iouv[NG];
    float best = -1.0f; int bg = 0;
    if (act){
        float bx1 = g_anc[n*4+0], by1 = g_anc[n*4+1], bx2 = g_anc[n*4+2], by2 = g_anc[n*4+3];
        #pragma unroll
        for (int g = 0; g < NG; g++){
            float v = iou_pair(sgt[g*4+0], sgt[g*4+1], sgt[g*4+2], sgt[g*4+3],
                               bx1, by1, bx2, by2);
            iouv[g] = v;
            if (v > best){ best = v; bg = g; }
        }
    }
    #pragma unroll
    for (int g = 0; g < NG; g++){
        u64 pk = act ? ((((u64)(~asc_map(iouv[g]))) << 32) | (u32)n) : ~0ull;
        #pragma unroll
        for (int o = 16; o > 0; o >>= 1){
            u64 other = __shfl_down_sync(0xffffffffu, pk, o);
            pk = (other < pk) ? other : pk;
        }
        if (lane == 0) atomicMin((unsigned long long*)&sbest[g], (unsigned long long)pk);
    }
    __syncthreads();
    if (threadIdx.x < NG)
        atomicMin((unsigned long long*)&g_gtmin[b*NG + threadIdx.x],
                  (unsigned long long)sbest[threadIdx.x]);

    if (!act) return;
    int lab = -1;
    if (best < 0.3f) lab = 0;
    if (best >= 0.7f) lab = 1;
    if (g_inside[n]) lab = -1;
    size_t idx = (size_t)b*NAC + n;
    g_lab[idx] = lab;
    g_arg[idx] = (unsigned char)bg;
    u32 bits = tf_bits((u32)idx);
    g_R[idx] = ((u64)(bits >> 9) << 32) | (u32)n;
}

// ---------------- B2: gt-apply + count + sampling threshold ----------------
__global__ void __launch_bounds__(1024) k_select(){
    __shared__ u32 hist[256];
    __shared__ u32 s_bin, s_rem;
    __shared__ int scp, scn;
    int b = blockIdx.x >> 1, c = blockIdx.x & 1;
    int* lab = g_lab + (size_t)b*NAC;
    // gt-apply prologue (idempotent same-value writes by both blocks of image b)
    if (threadIdx.x < NG){
        u64 v = g_gtmin[b*NG + threadIdx.x];
        int n = (int)(v & 0xFFFFFFFFull);
        if (!g_inside[n]) lab[n] = 1;
    }
    if (threadIdx.x == 0){ scp = 0; scn = 0; }
    __syncthreads();
    int cp = 0, cn = 0;
    for (int e = threadIdx.x; e < NAC; e += blockDim.x){
        int l = lab[e];
        cp += (l == 1); cn += (l == 0);
    }
    #pragma unroll
    for (int o = 16; o > 0; o >>= 1){
        cp += __shfl_down_sync(0xffffffffu, cp, o);
        cn += __shfl_down_sync(0xffffffffu, cn, o);
    }
    if ((threadIdx.x & 31) == 0){ atomicAdd(&scp, cp); atomicAdd(&scn, cn); }
    __syncthreads();
    int np = min(scp, 128);
    int nn = min(scn, 256 - np);
    int want = (c == 0) ? 1 : 0;
    unsigned k = (c == 0) ? (unsigned)np : (unsigned)nn;
    u64 thr = 0;
    if (k > 0)
        thr = kth_gen(g_R + (size_t)b*NAC, lab, want, k, BPS_R, 5, hist, &s_bin, &s_rem);
    if (threadIdx.x == 0){
        if (c == 0){ g_posthr[b] = thr; g_npos[b] = np; }
        else       { g_negthr[b] = thr; g_nneg[b] = nn; }
    }
}

// ---------------- A2: top-2000 select + sort + gather boxes ----------------
__global__ void __launch_bounds__(1024) k_topk(){
    __shared__ u32 hist[256];
    __shared__ u32 s_bin, s_rem;
    __shared__ unsigned scnt;
    __shared__ u64 buf[2048];
    int b = blockIdx.x, tid = threadIdx.x;
    const u64* keys = g_K + (size_t)b*NAC;
    u64 thr = kth_gen(keys, nullptr, 0, (unsigned)PRE, BPS_K, 6, hist, &s_bin, &s_rem);
    if (tid == 0) scnt = 0;
    __syncthreads();
    for (int e = tid; e < NAC; e += blockDim.x){
        u64 key = keys[e];
        if (key <= thr){ unsigned p = atomicAdd(&scnt, 1u); buf[p] = key; }
    }
    __syncthreads();
    for (int e = PRE + tid; e < 2048; e += blockDim.x) buf[e] = ~0ull;
    __syncthreads();
    for (unsigned k2 = 2; k2 <= 2048; k2 <<= 1){
        for (unsigned j = k2 >> 1; j > 0; j >>= 1){
            for (unsigned i = tid; i < 2048; i += blockDim.x){
                unsigned ixj = i ^ j;
                if (ixj > i){
                    bool up = ((i & k2) == 0);
                    u64 a = buf[i], cc = buf[ixj];
                    if ((a > cc) == up){ buf[i] = cc; buf[ixj] = a; }
                }
            }
            __syncthreads();
        }
    }
    for (int t = tid; t < PRE; t += blockDim.x){
        int n = (int)(buf[t] & 0xFFFFFFFFull);
        float4 v = *(const float4*)(g_prop + ((size_t)b*NAC + n)*4);
        *(float4*)(g_sbox + ((size_t)b*PRE + t)*4) = v;
    }
}

// ---------------- A3: NMS suppression bitmask (upper triangle only) --------
__global__ void k_mask(){
    __shared__ float sx1[PRE], sy1[PRE], sx2[PRE], sy2[PRE];
    int b = blockIdx.y, tile = blockIdx.x;
    const float* sb = g_sbox + (size_t)b*PRE*4;
    for (int j = threadIdx.x; j < PRE; j += blockDim.x){
        float4 v = ((const float4*)sb)[j];
        sx1[j]=v.x; sy1[j]=v.y; sx2[j]=v.z; sy2[j]=v.w;
    }
    __syncthreads();
    int warp = threadIdx.x >> 5, lane = threadIdx.x & 31;
    for (int rr = 0; rr < 4; rr++){
        int i = tile*32 + warp*4 + rr;
        if (i >= PRE) continue;
        float ax1 = sx1[i], ay1 = sy1[i], ax2 = sx2[i], ay2 = sy2[i];
        u32* out = g_nmsmask + ((size_t)b*PRE + i)*64;
        int cj0 = i >> 5;
        for (int cj = lane; cj < cj0; cj += 32) out[cj] = 0u;
        for (int cj = cj0; cj < 63; cj++){
            int j = cj*32 + lane;
            bool bit = false;
            if (j < PRE && j > i){
                float iou = iou_pair(ax1, ay1, ax2, ay2, sx1[j], sy1[j], sx2[j], sy2[j]);
                bit = iou > 0.7f;
            }
            u32 word = __ballot_sync(0xffffffffu, bit);
            if (lane == 0) out[cj] = word;
        }
        if (lane == 0) out[63] = 0u;
    }
}

// ---------------- A4: greedy NMS reduce + box output -----------------------
__global__ void k_nmsred(float* __restrict__ outb){
    __shared__ int skeep[POST];
    int b = blockIdx.x, lane = threadIdx.x;
    u64 rem = (lane == 31) ? ~((1ull << (PRE - 1984)) - 1ull) : 0ull;
    int cnt = 0, cur = 0;
    const u32* mbase = g_nmsmask + (size_t)b*PRE*64;
    // prime L1 with the first 16 rows
    {
        int pr = (lane >> 1);
        const char* p = (const char*)(mbase) + (size_t)pr*256 + (lane & 1)*128;
        asm volatile("prefetch.global.L1 [%0];" :: "l"(p));
    }
    while (cnt < POST){
        u64 myw = rem;
        int base = lane*64;
        if (cur >= base + 64) myw = ~0ull;
        else if (cur > base){
            int sh = cur - base;
            myw |= ((1ull << sh) - 1ull);
        }
        u32 bal = __ballot_sync(0xffffffffu, myw != ~0ull);
        if (!bal) break;
        int src = __ffs(bal) - 1;
        u64 w = __shfl_sync(0xffffffffu, myw, src);
        int bit = __ffsll((long long)~w) - 1;
        int i = src*64 + bit;
        if (lane == 0) skeep[cnt] = i;
        cnt++;
        if (cnt >= POST) break;
        // prefetch rows i+1 .. i+16 into L1 (next kept is usually nearby)
        {
            int pr = i + 1 + (lane >> 1);
            if (pr > PRE-1) pr = PRE-1;
            const char* p = (const char*)(mbase) + (size_t)pr*256 + (lane & 1)*128;
            asm volatile("prefetch.global.L1 [%0];" :: "l"(p));
        }
        const u64* row64 = (const u64*)(mbase + (size_t)i*64);
        rem |= __ldg(row64 + lane);
        cur = i + 1;
    }
    __syncwarp();
    for (int j = lane; j < POST; j += 32){
        float4 v = make_float4(0.f, 0.f, 0.f, 0.f);
        if (j < cnt){
            int i = skeep[j];
            const float4 p = *(const float4*)(g_sbox + ((size_t)b*PRE + i)*4);
            v = make_float4(floorf(p.x), floorf(p.y), floorf(p.z), floorf(p.w));
        }
        ((float4*)outb)[b*POST + j] = v;
    }
}

// ---------------- B3: losses with inline sampled labels --------------------
__global__ void k_loss(const float* __restrict__ pred, const float* __restrict__ cls,
                       const float* __restrict__ gt){
    __shared__ double s1[256], s2[256];
    int b = blockIdx.y;
    int n = blockIdx.x*blockDim.x + threadIdx.x;
    double cacc = 0.0, bacc = 0.0;
    if (n < NAC){
        size_t idx = (size_t)b*NAC + n;
        int lab0 = g_lab[idx];
        u64 R = g_R[idx];
        int lab = -1;
        if (lab0 == 1 && g_npos[b] > 0 && R <= g_posthr[b]) lab = 1;
        else if (lab0 == 0 && g_nneg[b] > 0 && R <= g_negthr[b]) lab = 0;
        int hw = n / 9, a = n % 9, h = hw / 50, w = hw % 50;
        if (lab != -1){
            float x0 = cls[(((size_t)b*18 + a*2    )*50 + h)*50 + w];
            float x1 = cls[(((size_t)b*18 + a*2 + 1)*50 + h)*50 + w];
            float m = fmaxf(x0, x1);
            float l = logf(__fadd_rn(expf(__fsub_rn(x0, m)), expf(__fsub_rn(x1, m))));
            float sel = (lab == 1) ? x1 : x0;
            cacc = (double)__fsub_rn(l, __fsub_rn(sel, m));
        }
        if (lab == 1){
            float pd[4];
            size_t pbase = (((size_t)b*36 + (size_t)a*4)*50 + h)*50 + w;
            pd[0]=pred[pbase]; pd[1]=pred[pbase+2500]; pd[2]=pred[pbase+5000]; pd[3]=pred[pbase+7500];
            float ax = g_actr[n*4+0], ay = g_actr[n*4+1], aw = g_actr[n*4+2], ah = g_actr[n*4+3];
            int gi = g_arg[idx];
            const float* g4 = gt + ((size_t)b*NG + gi)*4;
            float gx = __fmul_rn(__fadd_rn(g4[0], g4[2]), 0.5f);
            float gy = __fmul_rn(__fadd_rn(g4[1], g4[3]), 0.5f);
            float gw = __fsub_rn(g4[2], g4[0]);
            float gh = __fsub_rn(g4[3], g4[1]);
            float tt[4];
            tt[0] = __fdiv_rn(__fsub_rn(gx, ax), aw);
            tt[1] = __fdiv_rn(__fsub_rn(gy, ay), ah);
            tt[2] = logf(__fdiv_rn(gw, aw));
            tt[3] = logf(__fdiv_rn(gh, ah));
            const float C1 = (float)(1.0/9.0), C2 = (float)(0.5/9.0);
            double s = 0.0;
            #pragma unroll
            for (int k = 0; k < 4; k++){
                float d = __fsub_rn(pd[k], tt[k]);
                float ad = fabsf(d);
                float l1 = (ad < C1) ? __fmul_rn(__fmul_rn(4.5f, d), d) : __fsub_rn(ad, C2);
                s += (double)l1;
            }
            bacc = s;
        }
    }
    s1[threadIdx.x] = cacc; s2[threadIdx.x] = bacc;
    __syncthreads();
    for (int o = 128; o > 0; o >>= 1){
        if (threadIdx.x < o){ s1[threadIdx.x]+=s1[threadIdx.x+o]; s2[threadIdx.x]+=s2[threadIdx.x+o]; }
        __syncthreads();
    }
    if (threadIdx.x == 0){
        int pb = b*GRIDX + blockIdx.x;
        g_partC[pb] = s1[0];
        g_partB[pb] = s2[0];
    }
}

__global__ void k_lossfin(float* __restrict__ out){
    __shared__ double s1[256], s2[256];
    double a = 0.0, c = 0.0;
    for (int i = threadIdx.x; i < NPART; i += blockDim.x){
        a += g_partC[i]; c += g_partB[i];
    }
    s1[threadIdx.x] = a; s2[threadIdx.x] = c;
    __syncthreads();
    for (int o = 128; o > 0; o >>= 1){
        if (threadIdx.x < o){ s1[threadIdx.x]+=s1[threadIdx.x+o]; s2[threadIdx.x]+=s2[threadIdx.x+o]; }
        __syncthreads();
    }
    if (threadIdx.x == 0){
        int tot = 0;
        for (int b = 0; b < NB; b++) tot += g_npos[b] + g_nneg[b];
        if (tot < 1) tot = 1;
        int N0 = g_npos[0] + g_nneg[0];
        if (N0 < 1) N0 = 1;
        out[NB*POST*4 + 0] = (float)(s2[0] / (double)N0);   // bbox_loss
        out[NB*POST*4 + 1] = (float)(s1[0] / (double)tot);  // cls_loss
    }
}

// ---------------- launch: fork-join two independent chains -----------------
extern "C" void kernel_launch(void* const* d_in, const int* in_sizes, int n_in,
                              void* d_out, int out_size){
    const float* pred = (const float*)d_in[0];
    const float* cls  = (const float*)d_in[1];
    const float* gt   = (const float*)d_in[2];
    float* out = (float*)d_out;
    (void)in_sizes; (void)n_in; (void)out_size;

    // one-time side stream + events (created on first, non-captured call)
    static cudaStream_t sB = [](){
        cudaStream_t s; cudaStreamCreateWithFlags(&s, cudaStreamNonBlocking); return s;
    }();
    static cudaEvent_t eFork = [](){
        cudaEvent_t e; cudaEventCreateWithFlags(&e, cudaEventDisableTiming); return e;
    }();
    static cudaEvent_t eJoin = [](){
        cudaEvent_t e; cudaEventCreateWithFlags(&e, cudaEventDisableTiming); return e;
    }();

    k_init<<<GRIDX, 256>>>();
    cudaEventRecord(eFork, 0);
    cudaStreamWaitEvent(sB, eFork, 0);

    // chain B (labels / sampling / losses) on side stream
    k_labels <<<dim3(GRIDX, NB), 256, 0, sB>>>(gt);
    k_select <<<NB*2, 1024, 0, sB>>>();
    k_loss   <<<dim3(GRIDX, NB), 256, 0, sB>>>(pred, cls, gt);
    k_lossfin<<<1, 256, 0, sB>>>(out);
    cudaEventRecord(eJoin, sB);

    // chain A (proposals / NMS) on the capture stream
    k_decode<<<dim3(GRIDX, NB), 256>>>(pred, cls);
    k_topk  <<<NB, 1024>>>();
    k_mask  <<<dim3(63, NB), 256>>>();
    k_nmsred<<<NB, 32>>>(out);

    cudaStreamWaitEvent(0, eJoin, 0);
}

// round 8
// speedup vs baseline: 2.1185x; 1.0005x over previous
#include <cuda_runtime.h>
#include <stdint.h>
#include <math.h>

typedef unsigned int u32;
typedef unsigned long long u64;

#define NB    8
#define NAC   22500
#define NG    20
#define PRE   2000
#define POST  300
#define GRIDX 88                 // ceil(22500/256)
#define NPART (NB*GRIDX)         // 704
#define NBIN  65536

// ---------------- device scratch (no allocations allowed) ----------------
__device__ float g_anc[NAC*4];          // anchors xyxy
__device__ float g_actr[NAC*4];         // anchors cx,cy,w,h
__device__ unsigned char g_inside[NAC];
__device__ float g_prop[NB*NAC*4];      // clipped proposals
__device__ u64   g_K[NB*NAC];           // topk composite keys
__device__ u64   g_R[NB*NAC];           // rng composite keys
__device__ int   g_lab[NB*NAC];         // labels (pre-sample + gt-forced)
__device__ unsigned char g_arg[NB*NAC]; // argmax gt per anchor
__device__ u64   g_gtmin[NB*NG];        // per-gt best anchor (packed min)
__device__ u32   g_histK[NB*NBIN];      // score-key top16 histogram
__device__ u32   g_histP[NB*NBIN];      // rng-key top16 histogram (pos)
__device__ u32   g_histN[NB*NBIN];      // rng-key top16 histogram (neg)
__device__ int   g_cpos[NB], g_cneg[NB];
__device__ int   g_npos[NB], g_nneg[NB];
__device__ u64   g_posthr[NB], g_negthr[NB];
__device__ float g_sbox[NB*PRE*4];      // sorted top-2000 boxes
__device__ u32   g_nmsmask[NB*PRE*64];  // suppression bitmask rows
__device__ double g_partC[NPART], g_partB[NPART];

// ---------------- helpers ----------------
__device__ __forceinline__ u32 asc_map(float f){
    u32 b = __float_as_uint(f);
    return (b & 0x80000000u) ? ~b : (b | 0x80000000u);
}

__device__ __forceinline__ float iou_pair(float ax1,float ay1,float ax2,float ay2,
                                          float bx1,float by1,float bx2,float by2){
    float tlx = fmaxf(ax1,bx1), tly = fmaxf(ay1,by1);
    float brx = fminf(ax2,bx2), bry = fminf(ay2,by2);
    float w = fmaxf(__fsub_rn(brx, tlx), 0.0f);
    float h = fmaxf(__fsub_rn(bry, tly), 0.0f);
    float inter = __fmul_rn(w, h);
    float a1 = __fmul_rn(__fsub_rn(ax2,ax1), __fsub_rn(ay2,ay1));
    float a2 = __fmul_rn(__fsub_rn(bx2,bx1), __fsub_rn(by2,by1));
    float den = fmaxf(__fsub_rn(__fadd_rn(a1, a2), inter), 1e-8f);
    return __fdiv_rn(inter, den);
}

// jax threefry2x32, PARTITIONABLE scheme: counter i -> (0, i); out = x0 ^ x1.
#define TFR(r) { x0 += x1; x1 = (x1<<(r))|(x1>>(32-(r))); x1 ^= x0; }
__device__ __forceinline__ u32 tf_bits(u32 flat){
    const u32 k0 = 0u, k1 = 42u;
    const u32 k2 = 0x1BD11BDAu ^ k0 ^ k1;
    u32 x0 = 0u, x1 = flat;
    x0 += k0; x1 += k1;
    TFR(13) TFR(15) TFR(26) TFR(6)
    x0 += k1; x1 += k2 + 1u;
    TFR(17) TFR(29) TFR(16) TFR(24)
    x0 += k2; x1 += k0 + 2u;
    TFR(13) TFR(15) TFR(26) TFR(6)
    x0 += k0; x1 += k1 + 3u;
    TFR(17) TFR(29) TFR(16) TFR(24)
    x0 += k1; x1 += k2 + 4u;
    TFR(13) TFR(15) TFR(26) TFR(6)
    x0 += k2; x1 += k0 + 5u;
    return x0 ^ x1;
}
#undef TFR

// block-wide (1024 thr): find bin B where cumulative hist count first reaches k.
// Each thread owns 64 consecutive bins. Returns (B, count_below_B) via smem.
__device__ void find_bin(const u32* __restrict__ hist, unsigned k,
                         u32* part, u32* wsum, u32* s_bin, u32* s_below){
    int tid = threadIdx.x, lane = tid & 31, wid = tid >> 5;
    u32 mysum = 0;
    #pragma unroll
    for (int j = 0; j < 64; j++) mysum += hist[tid*64 + j];
    u32 v = mysum;
    #pragma unroll
    for (int o = 1; o < 32; o <<= 1){
        u32 t = __shfl_up_sync(0xffffffffu, v, o);
        if (lane >= o) v += t;
    }
    if (lane == 31) wsum[wid] = v;
    __syncthreads();
    if (wid == 0){
        u32 wv = wsum[lane];
        #pragma unroll
        for (int o = 1; o < 32; o <<= 1){
            u32 t = __shfl_up_sync(0xffffffffu, wv, o);
            if (lane >= o) wv += t;
        }
        wsum[lane] = wv;
    }
    __syncthreads();
    u32 offset = (wid > 0) ? wsum[wid-1] : 0u;
    u32 incl = v + offset;
    u32 excl = incl - mysum;
    if (excl < k && k <= incl){
        u32 cum = excl;
        for (int j = 0; j < 64; j++){
            u32 c = hist[tid*64 + j];
            if (cum + c >= k){ *s_bin = (u32)(tid*64 + j); *s_below = cum; break; }
            cum += c;
        }
    }
    __syncthreads();
}

template<int N>
__device__ void bitonic_sort(u64* buf, int tid, int nthr){
    for (unsigned k2 = 2; k2 <= (unsigned)N; k2 <<= 1){
        for (unsigned j = k2 >> 1; j > 0; j >>= 1){
            for (unsigned i = tid; i < (unsigned)N; i += nthr){
                unsigned ixj = i ^ j;
                if (ixj > i){
                    bool up = ((i & k2) == 0);
                    u64 a = buf[i], c = buf[ixj];
                    if ((a > c) == up){ buf[i] = c; buf[ixj] = a; }
                }
            }
            __syncthreads();
        }
    }
}

// ---------------- K0: anchors + resets ----------------
__global__ void k_init(){
    int gid = blockIdx.x*blockDim.x + threadIdx.x;
    // zero the three histograms (as u64 pairs) + counters + gtmin
    u64* hz = (u64*)g_histK;  // histK, histP, histN are contiguous? not guaranteed — zero each
    (void)hz;
    for (int i = gid; i < NB*NBIN/2; i += GRIDX*256){
        ((u64*)g_histK)[i] = 0ull;
        ((u64*)g_histP)[i] = 0ull;
        ((u64*)g_histN)[i] = 0ull;
    }
    if (gid < NB*NG) g_gtmin[gid] = ~0ull;
    if (gid < NB){ g_cpos[gid] = 0; g_cneg[gid] = 0; }
    int n = gid;
    if (n >= NAC) return;
    int d = n / 2500, c = n % 2500;
    int si = d / 3, ri = d % 3;
    double s = (si==0) ? 8.0 : (si==1) ? 16.0 : 32.0;
    double r = (ri==0) ? 0.5 : (ri==1) ? 1.0 : 2.0;
    float d0 = (float)(16.0 * s * sqrt(r));
    float d1 = (float)(16.0 * s * sqrt(1.0 / r));
    float cx = (float)(8 + 16*(c/50));
    float cy = (float)(8 + 16*(c%50));
    float hx = __fmul_rn(0.5f, d0), hy = __fmul_rn(0.5f, d1);
    float x1 = __fsub_rn(cx, hx), y1 = __fsub_rn(cy, hy);
    float x2 = __fadd_rn(cx, hx), y2 = __fadd_rn(cy, hy);
    g_anc[n*4+0]=x1; g_anc[n*4+1]=y1; g_anc[n*4+2]=x2; g_anc[n*4+3]=y2;
    g_actr[n*4+0]=__fmul_rn(__fadd_rn(x1,x2),0.5f);
    g_actr[n*4+1]=__fmul_rn(__fadd_rn(y1,y2),0.5f);
    g_actr[n*4+2]=__fsub_rn(x2,x1);
    g_actr[n*4+3]=__fsub_rn(y2,y1);
    g_inside[n] = (x1 >= 0.0f) && (y1 >= 0.0f) && (x2 <= 800.0f) && (y2 <= 800.0f);
}

// ---------------- A1: decode proposals + score keys + hist -----------------
__global__ void k_decode(const float* __restrict__ pred, const float* __restrict__ cls){
    int n = blockIdx.x*blockDim.x + threadIdx.x;
    int b = blockIdx.y;
    if (n >= NAC) return;
    int hw = n / 9, a = n % 9, h = hw / 50, w = hw % 50;
    size_t pbase = (((size_t)b*36 + (size_t)a*4)*50 + h)*50 + w;
    float dx = pred[pbase], dy = pred[pbase+2500], dw = pred[pbase+5000], dh = pred[pbase+7500];
    float ax = g_actr[n*4+0], ay = g_actr[n*4+1], aw = g_actr[n*4+2], ah = g_actr[n*4+3];
    float px = __fadd_rn(ax, __fmul_rn(dx, aw));
    float py = __fadd_rn(ay, __fmul_rn(dy, ah));
    float pw = __fmul_rn(aw, expf(dw));
    float ph = __fmul_rn(ah, expf(dh));
    float hx = __fmul_rn(0.5f, pw), hy = __fmul_rn(0.5f, ph);
    float x1 = fminf(fmaxf(__fsub_rn(px, hx), 0.0f), 799.0f);
    float y1 = fminf(fmaxf(__fsub_rn(py, hy), 0.0f), 799.0f);
    float x2 = fminf(fmaxf(__fadd_rn(px, hx), 0.0f), 799.0f);
    float y2 = fminf(fmaxf(__fadd_rn(py, hy), 0.0f), 799.0f);
    size_t o = ((size_t)b*NAC + n)*4;
    *(float4*)(g_prop + o) = make_float4(x1, y1, x2, y2);
    float sc = cls[(((size_t)b*18 + 9 + a)*50 + h)*50 + w];
    u64 key = ((u64)(~asc_map(sc)) << 32) | (u32)n;
    g_K[(size_t)b*NAC + n] = key;
    atomicAdd(&g_histK[b*NBIN + (u32)(key >> 48)], 1u);
}

// ---------------- B1: labels + argmax + rng + per-gt best + hists ----------
__global__ void k_labels(const float* __restrict__ gt){
    __shared__ float sgt[NG*4];
    __shared__ u64 sbest[NG];
    int b = blockIdx.y;
    if (threadIdx.x < NG*4) sgt[threadIdx.x] = gt[(size_t)b*NG*4 + threadIdx.x];
    if (threadIdx.x < NG) sbest[threadIdx.x] = ~0ull;
    __syncthreads();
    int n = blockIdx.x*blockDim.x + threadIdx.x;
    bool act = (n < NAC);
    int lane = threadIdx.x & 31;

    float iouv[NG];
    float best = -1.0f; int bg = 0;
    if (act){
        float bx1 = g_anc[n*4+0], by1 = g_anc[n*4+1], bx2 = g_anc[n*4+2], by2 = g_anc[n*4+3];
        #pragma unroll
        for (int g = 0; g < NG; g++){
            float v = iou_pair(sgt[g*4+0], sgt[g*4+1], sgt[g*4+2], sgt[g*4+3],
                               bx1, by1, bx2, by2);
            iouv[g] = v;
            if (v > best){ best = v; bg = g; }
        }
    }
    #pragma unroll
    for (int g = 0; g < NG; g++){
        u64 pk = act ? ((((u64)(~asc_map(iouv[g]))) << 32) | (u32)n) : ~0ull;
        #pragma unroll
        for (int o = 16; o > 0; o >>= 1){
            u64 other = __shfl_down_sync(0xffffffffu, pk, o);
            pk = (other < pk) ? other : pk;
        }
        if (lane == 0) atomicMin((unsigned long long*)&sbest[g], (unsigned long long)pk);
    }
    __syncthreads();
    if (threadIdx.x < NG)
        atomicMin((unsigned long long*)&g_gtmin[b*NG + threadIdx.x],
                  (unsigned long long)sbest[threadIdx.x]);

    int lab = -1;
    size_t idx = (size_t)b*NAC + n;
    u64 R = 0;
    if (act){
        if (best < 0.3f) lab = 0;
        if (best >= 0.7f) lab = 1;
        if (g_inside[n]) lab = -1;
        g_lab[idx] = lab;
        g_arg[idx] = (unsigned char)bg;
        u32 bits = tf_bits((u32)idx);
        R = ((u64)(bits >> 9) << 32) | (u32)n;
        g_R[idx] = R;
        u32 bin = (u32)((R >> 39) & 0xFFFFull);
        if (lab == 0) atomicAdd(&g_histN[b*NBIN + bin], 1u);
        else if (lab == 1) atomicAdd(&g_histP[b*NBIN + bin], 1u);
    }
    // per-warp pos/neg counts -> global
    int cp = (act && lab == 1) ? 1 : 0;
    int cn = (act && lab == 0) ? 1 : 0;
    #pragma unroll
    for (int o = 16; o > 0; o >>= 1){
        cp += __shfl_down_sync(0xffffffffu, cp, o);
        cn += __shfl_down_sync(0xffffffffu, cn, o);
    }
    if (lane == 0){
        if (cp) atomicAdd(&g_cpos[b], cp);
        if (cn) atomicAdd(&g_cneg[b], cn);
    }
}

// ---------------- B2: apply per-gt best (dedup) + fix hists/counts ---------
__global__ void k_gtapply(){
    int b = threadIdx.x;
    if (b >= NB) return;
    int seen[NG]; int ns = 0;
    for (int g = 0; g < NG; g++){
        int n = (int)(g_gtmin[b*NG + g] & 0xFFFFFFFFull);
        bool dup = false;
        for (int s = 0; s < ns; s++) if (seen[s] == n) dup = true;
        seen[ns++] = n;
        if (dup || g_inside[n]) continue;
        size_t idx = (size_t)b*NAC + n;
        int old = g_lab[idx];
        if (old == 1) continue;
        g_lab[idx] = 1;
        u32 bin = (u32)((g_R[idx] >> 39) & 0xFFFFull);
        g_histP[b*NBIN + bin] += 1u;
        g_cpos[b] += 1;
        if (old == 0){
            g_histN[b*NBIN + bin] -= 1u;
            g_cneg[b] -= 1;
        }
    }
}

// ---------------- B3: sampling thresholds via hist16 + single scan ---------
__global__ void __launch_bounds__(1024) k_select(){
    __shared__ u32 part[1024];
    __shared__ u32 wsum[32];
    __shared__ u32 s_bin, s_below;
    __shared__ unsigned scnt;
    __shared__ u64 buf[512];
    int b = blockIdx.x >> 1, c = blockIdx.x & 1;
    int np = min(g_cpos[b], 128);
    int nn = min(g_cneg[b], 256 - np);
    int want = (c == 0) ? 1 : 0;
    unsigned k = (c == 0) ? (unsigned)np : (unsigned)nn;
    u64 thr = 0;
    if (k > 0){
        const u32* hist = ((c == 0) ? g_histP : g_histN) + b*NBIN;
        find_bin(hist, k, part, wsum, &s_bin, &s_below);
        u32 B = s_bin;
        if (threadIdx.x == 0) scnt = 0;
        __syncthreads();
        const int* lab = g_lab + (size_t)b*NAC;
        const u64* R = g_R + (size_t)b*NAC;
        for (int e = threadIdx.x; e < NAC; e += blockDim.x){
            if (lab[e] != want) continue;
            u64 key = R[e];
            if ((u32)((key >> 39) & 0xFFFFull) <= B){
                unsigned p = atomicAdd(&scnt, 1u);
                if (p < 512) buf[p] = key;
            }
        }
        __syncthreads();
        unsigned cnt = scnt;
        for (unsigned e = cnt + threadIdx.x; e < 512; e += blockDim.x) buf[e] = ~0ull;
        __syncthreads();
        bitonic_sort<512>(buf, threadIdx.x, blockDim.x);
        thr = buf[k-1];
    }
    if (threadIdx.x == 0){
        if (c == 0){ g_posthr[b] = thr; g_npos[b] = np; }
        else       { g_negthr[b] = thr; g_nneg[b] = nn; }
    }
}

// ---------------- A2: top-2000 via hist16 + single scan + sort -------------
__global__ void __launch_bounds__(1024) k_topk(){
    __shared__ u32 part[1024];
    __shared__ u32 wsum[32];
    __shared__ u32 s_bin, s_below;
    __shared__ unsigned scnt;
    __shared__ u64 buf[2048];
    int b = blockIdx.x, tid = threadIdx.x;
    const u64* keys = g_K + (size_t)b*NAC;
    find_bin(g_histK + b*NBIN, (unsigned)PRE, part, wsum, &s_bin, &s_below);
    u32 B = s_bin;
    if (tid == 0) scnt = 0;
    __syncthreads();
    for (int e = tid; e < NAC; e += blockDim.x){
        u64 key = keys[e];
        if ((u32)(key >> 48) <= B){
            unsigned p = atomicAdd(&scnt, 1u);
            if (p < 2048) buf[p] = key;
        }
    }
    __syncthreads();
    unsigned cnt = scnt;
    for (unsigned e = cnt + tid; e < 2048; e += blockDim.x) buf[e] = ~0ull;
    __syncthreads();
    bitonic_sort<2048>(buf, tid, blockDim.x);
    for (int t = tid; t < PRE; t += blockDim.x){
        int n = (int)(buf[t] & 0xFFFFFFFFull);
        float4 v = *(const float4*)(g_prop + ((size_t)b*NAC + n)*4);
        *(float4*)(g_sbox + ((size_t)b*PRE + t)*4) = v;
    }
}

// ---------------- A3: NMS suppression bitmask (upper triangle only) --------
__global__ void k_mask(){
    __shared__ float sx1[PRE], sy1[PRE], sx2[PRE], sy2[PRE];
    int b = blockIdx.y, tile = blockIdx.x;
    const float* sb = g_sbox + (size_t)b*PRE*4;
    for (int j = threadIdx.x; j < PRE; j += blockDim.x){
        float4 v = ((const float4*)sb)[j];
        sx1[j]=v.x; sy1[j]=v.y; sx2[j]=v.z; sy2[j]=v.w;
    }
    __syncthreads();
    int warp = threadIdx.x >> 5, lane = threadIdx.x & 31;
    for (int rr = 0; rr < 4; rr++){
        int i = tile*32 + warp*4 + rr;
        if (i >= PRE) continue;
        float ax1 = sx1[i], ay1 = sy1[i], ax2 = sx2[i], ay2 = sy2[i];
        u32* out = g_nmsmask + ((size_t)b*PRE + i)*64;
        int cj0 = i >> 5;
        for (int cj = lane; cj < cj0; cj += 32) out[cj] = 0u;
        for (int cj = cj0; cj < 63; cj++){
            int j = cj*32 + lane;
            bool bit = false;
            if (j < PRE && j > i){
                float iou = iou_pair(ax1, ay1, ax2, ay2, sx1[j], sy1[j], sx2[j], sy2[j]);
                bit = iou > 0.7f;
            }
            u32 word = __ballot_sync(0xffffffffu, bit);
            if (lane == 0) out[cj] = word;
        }
        if (lane == 0) out[63] = 0u;
    }
}

// ---------------- A4: greedy NMS reduce + box output -----------------------
__global__ void k_nmsred(float* __restrict__ outb){
    __shared__ int skeep[POST];
    int b = blockIdx.x, lane = threadIdx.x;
    u64 rem = (lane == 31) ? ~((1ull << (PRE - 1984)) - 1ull) : 0ull;
    int cnt = 0, cur = 0;
    const u32* mbase = g_nmsmask + (size_t)b*PRE*64;
    {
        int pr = (lane >> 1);
        const char* p = (const char*)(mbase) + (size_t)pr*256 + (lane & 1)*128;
        asm volatile("prefetch.global.L1 [%0];" :: "l"(p));
    }
    while (cnt < POST){
        u64 myw = rem;
        int base = lane*64;
        if (cur >= base + 64) myw = ~0ull;
        else if (cur > base){
            int sh = cur - base;
            myw |= ((1ull << sh) - 1ull);
        }
        u32 bal = __ballot_sync(0xffffffffu, myw != ~0ull);
        if (!bal) break;
        int src = __ffs(bal) - 1;
        u64 w = __shfl_sync(0xffffffffu, myw, src);
        int bit = __ffsll((long long)~w) - 1;
        int i = src*64 + bit;
        if (lane == 0) skeep[cnt] = i;
        cnt++;
        if (cnt >= POST) break;
        {
            int pr = i + 1 + (lane >> 1);
            if (pr > PRE-1) pr = PRE-1;
            const char* p = (const char*)(mbase) + (size_t)pr*256 + (lane & 1)*128;
            asm volatile("prefetch.global.L1 [%0];" :: "l"(p));
        }
        const u64* row64 = (const u64*)(mbase + (size_t)i*64);
        rem |= __ldg(row64 + lane);
        cur = i + 1;
    }
    __syncwarp();
    for (int j = lane; j < POST; j += 32){
        float4 v = make_float4(0.f, 0.f, 0.f, 0.f);
        if (j < cnt){
            int i = skeep[j];
            const float4 p = *(const float4*)(g_sbox + ((size_t)b*PRE + i)*4);
            v = make_float4(floorf(p.x), floorf(p.y), floorf(p.z), floorf(p.w));
        }
        ((float4*)outb)[b*POST + j] = v;
    }
}

// ---------------- B4: losses with inline sampled labels --------------------
__global__ void k_loss(const float* __restrict__ pred, const float* __restrict__ cls,
                       const float* __restrict__ gt){
    __shared__ double s1[256], s2[256];
    int b = blockIdx.y;
    int n = blockIdx.x*blockDim.x + threadIdx.x;
    double cacc = 0.0, bacc = 0.0;
    if (n < NAC){
        size_t idx = (size_t)b*NAC + n;
        int lab0 = g_lab[idx];
        u64 R = g_R[idx];
        int lab = -1;
        if (lab0 == 1 && g_npos[b] > 0 && R <= g_posthr[b]) lab = 1;
        else if (lab0 == 0 && g_nneg[b] > 0 && R <= g_negthr[b]) lab = 0;
        int hw = n / 9, a = n % 9, h = hw / 50, w = hw % 50;
        if (lab != -1){
            float x0 = cls[(((size_t)b*18 + a*2    )*50 + h)*50 + w];
            float x1 = cls[(((size_t)b*18 + a*2 + 1)*50 + h)*50 + w];
            float m = fmaxf(x0, x1);
            float l = logf(__fadd_rn(expf(__fsub_rn(x0, m)), expf(__fsub_rn(x1, m))));
            float sel = (lab == 1) ? x1 : x0;
            cacc = (double)__fsub_rn(l, __fsub_rn(sel, m));
        }
        if (lab == 1){
            float pd[4];
            size_t pbase = (((size_t)b*36 + (size_t)a*4)*50 + h)*50 + w;
            pd[0]=pred[pbase]; pd[1]=pred[pbase+2500]; pd[2]=pred[pbase+5000]; pd[3]=pred[pbase+7500];
            float ax = g_actr[n*4+0], ay = g_actr[n*4+1], aw = g_actr[n*4+2], ah = g_actr[n*4+3];
            int gi = g_arg[idx];
            const float* g4 = gt + ((size_t)b*NG + gi)*4;
            float gx = __fmul_rn(__fadd_rn(g4[0], g4[2]), 0.5f);
            float gy = __fmul_rn(__fadd_rn(g4[1], g4[3]), 0.5f);
            float gw = __fsub_rn(g4[2], g4[0]);
            float gh = __fsub_rn(g4[3], g4[1]);
            float tt[4];
            tt[0] = __fdiv_rn(__fsub_rn(gx, ax), aw);
            tt[1] = __fdiv_rn(__fsub_rn(gy, ay), ah);
            tt[2] = logf(__fdiv_rn(gw, aw));
            tt[3] = logf(__fdiv_rn(gh, ah));
            const float C1 = (float)(1.0/9.0), C2 = (float)(0.5/9.0);
            double s = 0.0;
            #pragma unroll
            for (int k = 0; k < 4; k++){
                float d = __fsub_rn(pd[k], tt[k]);
                float ad = fabsf(d);
                float l1 = (ad < C1) ? __fmul_rn(__fmul_rn(4.5f, d), d) : __fsub_rn(ad, C2);
                s += (double)l1;
            }
            bacc = s;
        }
    }
    s1[threadIdx.x] = cacc; s2[threadIdx.x] = bacc;
    __syncthreads();
    for (int o = 128; o > 0; o >>= 1){
        if (threadIdx.x < o){ s1[threadIdx.x]+=s1[threadIdx.x+o]; s2[threadIdx.x]+=s2[threadIdx.x+o]; }
        __syncthreads();
    }
    if (threadIdx.x == 0){
        int pb = b*GRIDX + blockIdx.x;
        g_partC[pb] = s1[0];
        g_partB[pb] = s2[0];
    }
}

__global__ void k_lossfin(float* __restrict__ out){
    __shared__ double s1[256], s2[256];
    double a = 0.0, c = 0.0;
    for (int i = threadIdx.x; i < NPART; i += blockDim.x){
        a += g_partC[i]; c += g_partB[i];
    }
    s1[threadIdx.x] = a; s2[threadIdx.x] = c;
    __syncthreads();
    for (int o = 128; o > 0; o >>= 1){
        if (threadIdx.x < o){ s1[threadIdx.x]+=s1[threadIdx.x+o]; s2[threadIdx.x]+=s2[threadIdx.x+o]; }
        __syncthreads();
    }
    if (threadIdx.x == 0){
        int tot = 0;
        for (int b = 0; b < NB; b++) tot += g_npos[b] + g_nneg[b];
        if (tot < 1) tot = 1;
        int N0 = g_npos[0] + g_nneg[0];
        if (N0 < 1) N0 = 1;
        out[NB*POST*4 + 0] = (float)(s2[0] / (double)N0);   // bbox_loss
        out[NB*POST*4 + 1] = (float)(s1[0] / (double)tot);  // cls_loss
    }
}

// ---------------- launch: fork-join two independent chains -----------------
extern "C" void kernel_launch(void* const* d_in, const int* in_sizes, int n_in,
                              void* d_out, int out_size){
    const float* pred = (const float*)d_in[0];
    const float* cls  = (const float*)d_in[1];
    const float* gt   = (const float*)d_in[2];
    float* out = (float*)d_out;
    (void)in_sizes; (void)n_in; (void)out_size;

    static cudaStream_t sB = [](){
        cudaStream_t s; cudaStreamCreateWithFlags(&s, cudaStreamNonBlocking); return s;
    }();
    static cudaEvent_t eFork = [](){
        cudaEvent_t e; cudaEventCreateWithFlags(&e, cudaEventDisableTiming); return e;
    }();
    static cudaEvent_t eJoin = [](){
        cudaEvent_t e; cudaEventCreateWithFlags(&e, cudaEventDisableTiming); return e;
    }();

    k_init<<<GRIDX, 256>>>();
    cudaEventRecord(eFork, 0);
    cudaStreamWaitEvent(sB, eFork, 0);

    // chain B (labels / sampling / losses) on side stream
    k_labels <<<dim3(GRIDX, NB), 256, 0, sB>>>(gt);
    k_gtapply<<<1, NB, 0, sB>>>();
    k_select <<<NB*2, 1024, 0, sB>>>();
    k_loss   <<<dim3(GRIDX, NB), 256, 0, sB>>>(pred, cls, gt);
    k_lossfin<<<1, 256, 0, sB>>>(out);
    cudaEventRecord(eJoin, sB);

    // chain A (proposals / NMS) on the capture stream
    k_decode<<<dim3(GRIDX, NB), 256>>>(pred, cls);
    k_topk  <<<NB, 1024>>>();
    k_mask  <<<dim3(63, NB), 256>>>();
    k_nmsred<<<NB, 32>>>(out);

    cudaStreamWaitEvent(0, eJoin, 0);
}